// round 1
// baseline (speedup 1.0000x reference)
#include <cuda_runtime.h>
#include <cstdint>

#define N_NODES 50000
#define N_EDGES 800000
#define IN_DIM  256
#define HEADS   4
#define OUT_DIM 64
#define FDIM    256            // HEADS * OUT_DIM
#define ALPHA   0.2f

// ---------------- scratch (static device globals; no allocation) -------------
__device__ float    g_ft  [N_NODES * FDIM];     // projected features  [N,256]
__device__ float    g_a1  [N_NODES * HEADS];    // src-side attn term  [N,4]
__device__ float    g_a2  [N_NODES * HEADS];    // dst-side attn term  [N,4]
__device__ float    g_score[N_EDGES * HEADS];   // leakyrelu scores    [E,4]
__device__ unsigned g_mkey[N_NODES * HEADS];    // segment max (ordered-uint enc)
__device__ float    g_ssum[N_NODES * HEADS];    // segment sum of exp

// order-preserving float<->uint encoding for atomicMax on floats (any sign)
__device__ __forceinline__ unsigned fenc(float f) {
    unsigned u = __float_as_uint(f);
    return (u & 0x80000000u) ? ~u : (u | 0x80000000u);
}
__device__ __forceinline__ float fdec(unsigned k) {
    return (k & 0x80000000u) ? __uint_as_float(k ^ 0x80000000u)
                             : __uint_as_float(~k);
}

// ---------------- 0) init: zero out, reset mkey/ssum ------------------------
__global__ void init_kernel(float* __restrict__ out) {
    int i = blockIdx.x * blockDim.x + threadIdx.x;
    if (i < N_NODES * FDIM) out[i] = 0.0f;
    if (i < N_NODES * HEADS) { g_mkey[i] = 0u; g_ssum[i] = 0.0f; }
}

// ---------------- 1) GEMM: ft[m,n] = sum_k feat[m,k] * W[n,k] ---------------
// classic 128x128x8 register-tiled SGEMM, 256 threads, TM=TN=8
#define BM 128
#define BN 128
#define BK 8
#define TM 8
#define TN 8
__global__ __launch_bounds__(256)
void gemm_kernel(const float* __restrict__ A,   // [M,K] feat
                 const float* __restrict__ Wm)  // [N,K] W
{
    const int M = N_NODES, N = FDIM, K = IN_DIM;
    __shared__ float As[BK][BM];
    __shared__ float Bs[BK][BN];

    const int tid = threadIdx.x;
    const int block_row = blockIdx.x * BM;
    const int block_col = blockIdx.y * BN;
    const int tx = tid & 15;          // 0..15
    const int ty = tid >> 4;          // 0..15

    const int ld_row = tid >> 1;      // 0..127
    const int ld_k4  = (tid & 1) * 4; // 0 or 4

    float acc[TM][TN];
#pragma unroll
    for (int i = 0; i < TM; i++)
#pragma unroll
        for (int j = 0; j < TN; j++) acc[i][j] = 0.0f;

    for (int k0 = 0; k0 < K; k0 += BK) {
        // load A tile (guard M edge), store transposed
        {
            int ar = block_row + ld_row;
            float4 av = make_float4(0.f, 0.f, 0.f, 0.f);
            if (ar < M)
                av = *reinterpret_cast<const float4*>(A + (size_t)ar * K + k0 + ld_k4);
            As[ld_k4 + 0][ld_row] = av.x;
            As[ld_k4 + 1][ld_row] = av.y;
            As[ld_k4 + 2][ld_row] = av.z;
            As[ld_k4 + 3][ld_row] = av.w;
        }
        // load B tile from W (N=256 divisible by BN, no guard)
        {
            int br = block_col + ld_row;
            float4 bv = *reinterpret_cast<const float4*>(Wm + (size_t)br * K + k0 + ld_k4);
            Bs[ld_k4 + 0][ld_row] = bv.x;
            Bs[ld_k4 + 1][ld_row] = bv.y;
            Bs[ld_k4 + 2][ld_row] = bv.z;
            Bs[ld_k4 + 3][ld_row] = bv.w;
        }
        __syncthreads();

#pragma unroll
        for (int k = 0; k < BK; k++) {
            float ra[TM], rb[TN];
#pragma unroll
            for (int i = 0; i < TM; i++) ra[i] = As[k][ty * TM + i];
#pragma unroll
            for (int j = 0; j < TN; j++) rb[j] = Bs[k][tx * TN + j];
#pragma unroll
            for (int i = 0; i < TM; i++)
#pragma unroll
                for (int j = 0; j < TN; j++) acc[i][j] = fmaf(ra[i], rb[j], acc[i][j]);
        }
        __syncthreads();
    }

#pragma unroll
    for (int i = 0; i < TM; i++) {
        int row = block_row + ty * TM + i;
        if (row < M) {
            float* cp = g_ft + (size_t)row * N + block_col + tx * TN;
            float4 v0 = make_float4(acc[i][0], acc[i][1], acc[i][2], acc[i][3]);
            float4 v1 = make_float4(acc[i][4], acc[i][5], acc[i][6], acc[i][7]);
            *reinterpret_cast<float4*>(cp + 0) = v0;
            *reinterpret_cast<float4*>(cp + 4) = v1;
        }
    }
}

// ---------------- 2) per-node attention terms a1/a2 -------------------------
// one warp per (node, head): 64-wide dot products with attn_l / attn_r
__global__ void a1a2_kernel(const float* __restrict__ attn_l,
                            const float* __restrict__ attn_r)
{
    int gtid = blockIdx.x * blockDim.x + threadIdx.x;
    int warp = gtid >> 5;
    int lane = gtid & 31;
    if (warp >= N_NODES * HEADS) return;
    int n = warp >> 2;
    int h = warp & 3;
    const float* row = g_ft + (size_t)n * FDIM + h * OUT_DIM;
    const float* al  = attn_l + h * OUT_DIM;
    const float* ar  = attn_r + h * OUT_DIM;
    float v0 = row[lane], v1 = row[lane + 32];
    float s1 = v0 * al[lane] + v1 * al[lane + 32];
    float s2 = v0 * ar[lane] + v1 * ar[lane + 32];
#pragma unroll
    for (int o = 16; o > 0; o >>= 1) {
        s1 += __shfl_xor_sync(0xFFFFFFFFu, s1, o);
        s2 += __shfl_xor_sync(0xFFFFFFFFu, s2, o);
    }
    if (lane == 0) {
        g_a1[n * HEADS + h] = s1;
        g_a2[n * HEADS + h] = s2;
    }
}

// ---------------- 3) edge scores + segment max ------------------------------
__global__ void score_kernel(const int* __restrict__ src,
                             const int* __restrict__ dst)
{
    int i = blockIdx.x * blockDim.x + threadIdx.x;
    if (i >= N_EDGES * HEADS) return;
    int e = i >> 2, h = i & 3;
    int s = src[e], d = dst[e];
    float x = g_a1[s * HEADS + h] + g_a2[d * HEADS + h];
    x = (x > 0.0f) ? x : ALPHA * x;
    g_score[i] = x;
    atomicMax(&g_mkey[d * HEADS + h], fenc(x));
}

// ---------------- 4) exp + segment sum --------------------------------------
__global__ void expsum_kernel(const int* __restrict__ dst)
{
    int i = blockIdx.x * blockDim.x + threadIdx.x;
    if (i >= N_EDGES * HEADS) return;
    int e = i >> 2, h = i & 3;
    int d = dst[e];
    float m  = fdec(g_mkey[d * HEADS + h]);
    float ex = __expf(g_score[i] - m);
    atomicAdd(&g_ssum[d * HEADS + h], ex);
}

// ---------------- 5) weighted scatter aggregation ---------------------------
// thread per (edge, float4-chunk). Vector RED (red.global.add.v4.f32) to cut
// L2 atomic-op count 4x vs scalar atomicAdd.
__global__ void aggregate_kernel(const int* __restrict__ src,
                                 const int* __restrict__ dst,
                                 float* __restrict__ out)
{
    int i = blockIdx.x * blockDim.x + threadIdx.x;   // < E*64 = 51.2M
    if (i >= N_EDGES * (FDIM / 4)) return;
    int e  = i >> 6;
    int c4 = i & 63;        // which float4 of the 256-wide row
    int h  = c4 >> 4;       // 16 float4 chunks per head
    int s = src[e], d = dst[e];
    float m    = fdec(g_mkey[d * HEADS + h]);
    float coef = __expf(g_score[e * HEADS + h] - m) / g_ssum[d * HEADS + h];
    float4 v = *reinterpret_cast<const float4*>(g_ft + (size_t)s * FDIM + c4 * 4);
    float4 r = make_float4(v.x * coef, v.y * coef, v.z * coef, v.w * coef);
    float* p = out + (size_t)d * FDIM + c4 * 4;
    asm volatile("red.global.add.v4.f32 [%0], {%1,%2,%3,%4};"
                 :: "l"(p), "f"(r.x), "f"(r.y), "f"(r.z), "f"(r.w)
                 : "memory");
}

// ---------------- 6) ELU epilogue -------------------------------------------
__global__ void elu_kernel(float* __restrict__ out)
{
    int i = blockIdx.x * blockDim.x + threadIdx.x;
    if (i >= N_NODES * FDIM) return;
    float x = out[i];
    out[i] = (x > 0.0f) ? x : expm1f(x);
}

// ---------------- launch -----------------------------------------------------
extern "C" void kernel_launch(void* const* d_in, const int* in_sizes, int n_in,
                              void* d_out, int out_size)
{
    const float* feat   = (const float*)d_in[0];
    const int*   src    = (const int*)  d_in[1];
    const int*   dst    = (const int*)  d_in[2];
    const float* W      = (const float*)d_in[3];
    const float* attn_l = (const float*)d_in[4];
    const float* attn_r = (const float*)d_in[5];
    float* out = (float*)d_out;

    const int TPB = 256;

    // 0) init out / mkey / ssum
    init_kernel<<<(N_NODES * FDIM + TPB - 1) / TPB, TPB>>>(out);

    // 1) projection GEMM
    {
        dim3 grid((N_NODES + BM - 1) / BM, FDIM / BN);
        gemm_kernel<<<grid, 256>>>(feat, W);
    }

    // 2) a1/a2
    {
        int warps = N_NODES * HEADS;
        int threads = warps * 32;
        a1a2_kernel<<<(threads + TPB - 1) / TPB, TPB>>>(attn_l, attn_r);
    }

    // 3) scores + segment max
    score_kernel<<<(N_EDGES * HEADS + TPB - 1) / TPB, TPB>>>(src, dst);

    // 4) exp + segment sum
    expsum_kernel<<<(N_EDGES * HEADS + TPB - 1) / TPB, TPB>>>(dst);

    // 5) aggregation
    aggregate_kernel<<<(N_EDGES * (FDIM / 4) + TPB - 1) / TPB, TPB>>>(src, dst, out);

    // 6) ELU
    elu_kernel<<<(N_NODES * FDIM + TPB - 1) / TPB, TPB>>>(out);
}

// round 2
// speedup vs baseline: 1.2105x; 1.2105x over previous
#include <cuda_runtime.h>
#include <cstdint>
#include <cfloat>

#define N_NODES 50000
#define N_EDGES 800000
#define IN_DIM  256
#define HEADS   4
#define OUT_DIM 64
#define FDIM    256            // HEADS * OUT_DIM
#define ALPHA   0.2f

#define SCAN_TPB 256
#define SCAN_NB  ((N_NODES + SCAN_TPB - 1) / SCAN_TPB)   // 196

// ---------------- scratch (static device globals; no allocation) -------------
__device__ float g_ft [N_NODES * FDIM];      // projected features [N,256]
__device__ float g_a1 [N_NODES * HEADS];     // src-side attn term [N,4]
__device__ float g_a2 [N_NODES * HEADS];     // dst-side attn term [N,4]
__device__ int   g_deg     [N_NODES];        // in-degree histogram
__device__ int   g_rowstart[N_NODES + 1];    // CSR row offsets (by dst)
__device__ int   g_cursor  [N_NODES];        // scatter cursors
__device__ int   g_csr_src [N_EDGES];        // CSR payload: src node per slot
__device__ int   g_bsum [SCAN_NB];           // scan block sums
__device__ int   g_bscan[SCAN_NB];           // scanned block sums

// ---------------- 0) init ----------------------------------------------------
__global__ void init_kernel() {
    int i = blockIdx.x * blockDim.x + threadIdx.x;
    if (i < N_NODES) g_deg[i] = 0;
    if (i == 0) g_rowstart[N_NODES] = N_EDGES;
}

// ---------------- 1) GEMM: ft[m,n] = sum_k feat[m,k] * W[n,k] ----------------
#define BM 128
#define BN 128
#define BK 8
#define TM 8
#define TN 8
__global__ __launch_bounds__(256)
void gemm_kernel(const float* __restrict__ A,   // [M,K] feat
                 const float* __restrict__ Wm)  // [N,K] W
{
    const int M = N_NODES, N = FDIM, K = IN_DIM;
    __shared__ float As[BK][BM];
    __shared__ float Bs[BK][BN];

    const int tid = threadIdx.x;
    const int block_row = blockIdx.x * BM;
    const int block_col = blockIdx.y * BN;
    const int tx = tid & 15;
    const int ty = tid >> 4;
    const int ld_row = tid >> 1;
    const int ld_k4  = (tid & 1) * 4;

    float acc[TM][TN];
#pragma unroll
    for (int i = 0; i < TM; i++)
#pragma unroll
        for (int j = 0; j < TN; j++) acc[i][j] = 0.0f;

    for (int k0 = 0; k0 < K; k0 += BK) {
        {
            int ar = block_row + ld_row;
            float4 av = make_float4(0.f, 0.f, 0.f, 0.f);
            if (ar < M)
                av = *reinterpret_cast<const float4*>(A + (size_t)ar * K + k0 + ld_k4);
            As[ld_k4 + 0][ld_row] = av.x;
            As[ld_k4 + 1][ld_row] = av.y;
            As[ld_k4 + 2][ld_row] = av.z;
            As[ld_k4 + 3][ld_row] = av.w;
        }
        {
            int br = block_col + ld_row;
            float4 bv = *reinterpret_cast<const float4*>(Wm + (size_t)br * K + k0 + ld_k4);
            Bs[ld_k4 + 0][ld_row] = bv.x;
            Bs[ld_k4 + 1][ld_row] = bv.y;
            Bs[ld_k4 + 2][ld_row] = bv.z;
            Bs[ld_k4 + 3][ld_row] = bv.w;
        }
        __syncthreads();

#pragma unroll
        for (int k = 0; k < BK; k++) {
            float ra[TM], rb[TN];
#pragma unroll
            for (int i = 0; i < TM; i++) ra[i] = As[k][ty * TM + i];
#pragma unroll
            for (int j = 0; j < TN; j++) rb[j] = Bs[k][tx * TN + j];
#pragma unroll
            for (int i = 0; i < TM; i++)
#pragma unroll
                for (int j = 0; j < TN; j++) acc[i][j] = fmaf(ra[i], rb[j], acc[i][j]);
        }
        __syncthreads();
    }

#pragma unroll
    for (int i = 0; i < TM; i++) {
        int row = block_row + ty * TM + i;
        if (row < M) {
            float* cp = g_ft + (size_t)row * N + block_col + tx * TN;
            *reinterpret_cast<float4*>(cp + 0) =
                make_float4(acc[i][0], acc[i][1], acc[i][2], acc[i][3]);
            *reinterpret_cast<float4*>(cp + 4) =
                make_float4(acc[i][4], acc[i][5], acc[i][6], acc[i][7]);
        }
    }
}

// ---------------- 2) per-node attention terms a1/a2 --------------------------
__global__ void a1a2_kernel(const float* __restrict__ attn_l,
                            const float* __restrict__ attn_r)
{
    int gtid = blockIdx.x * blockDim.x + threadIdx.x;
    int warp = gtid >> 5;
    int lane = gtid & 31;
    if (warp >= N_NODES * HEADS) return;
    int n = warp >> 2;
    int h = warp & 3;
    const float* row = g_ft + (size_t)n * FDIM + h * OUT_DIM;
    const float* al  = attn_l + h * OUT_DIM;
    const float* ar  = attn_r + h * OUT_DIM;
    float v0 = row[lane], v1 = row[lane + 32];
    float s1 = v0 * al[lane] + v1 * al[lane + 32];
    float s2 = v0 * ar[lane] + v1 * ar[lane + 32];
#pragma unroll
    for (int o = 16; o > 0; o >>= 1) {
        s1 += __shfl_xor_sync(0xFFFFFFFFu, s1, o);
        s2 += __shfl_xor_sync(0xFFFFFFFFu, s2, o);
    }
    if (lane == 0) {
        g_a1[n * HEADS + h] = s1;
        g_a2[n * HEADS + h] = s2;
    }
}

// ---------------- 3) CSR build: histogram, scan, scatter ---------------------
__global__ void hist_kernel(const int* __restrict__ dst) {
    int e = blockIdx.x * blockDim.x + threadIdx.x;
    if (e < N_EDGES) atomicAdd(&g_deg[dst[e]], 1);
}

// block-local exclusive scan of g_deg -> g_rowstart, totals -> g_bsum
__global__ __launch_bounds__(SCAN_TPB)
void scan1_kernel() {
    __shared__ int s[SCAN_TPB];
    int tid = threadIdx.x;
    int i = blockIdx.x * SCAN_TPB + tid;
    int v = (i < N_NODES) ? g_deg[i] : 0;
    s[tid] = v;
    __syncthreads();
#pragma unroll
    for (int off = 1; off < SCAN_TPB; off <<= 1) {
        int t = (tid >= off) ? s[tid - off] : 0;
        __syncthreads();
        s[tid] += t;
        __syncthreads();
    }
    if (i < N_NODES) g_rowstart[i] = s[tid] - v;          // exclusive
    if (tid == SCAN_TPB - 1) g_bsum[blockIdx.x] = s[tid]; // block total
}

// single-block exclusive scan of block sums
__global__ __launch_bounds__(SCAN_TPB)
void scan2_kernel() {
    __shared__ int s[SCAN_TPB];
    int tid = threadIdx.x;
    int v = (tid < SCAN_NB) ? g_bsum[tid] : 0;
    s[tid] = v;
    __syncthreads();
#pragma unroll
    for (int off = 1; off < SCAN_TPB; off <<= 1) {
        int t = (tid >= off) ? s[tid - off] : 0;
        __syncthreads();
        s[tid] += t;
        __syncthreads();
    }
    if (tid < SCAN_NB) g_bscan[tid] = s[tid] - v;
}

// add block offsets; init cursors
__global__ __launch_bounds__(SCAN_TPB)
void scan3_kernel() {
    int i = blockIdx.x * SCAN_TPB + threadIdx.x;
    if (i < N_NODES) {
        int r = g_rowstart[i] + g_bscan[blockIdx.x];
        g_rowstart[i] = r;
        g_cursor[i] = r;
    }
}

__global__ void scatter_kernel(const int* __restrict__ src,
                               const int* __restrict__ dst) {
    int e = blockIdx.x * blockDim.x + threadIdx.x;
    if (e >= N_EDGES) return;
    int slot = atomicAdd(&g_cursor[dst[e]], 1);
    g_csr_src[slot] = src[e];
}

// ---------------- 4) fused per-dst-node GAT aggregation ----------------------
// 1 block per dst node, 256 threads = 1 feature column each.
// Pass A: segment max  Pass B: segment sum  Pass C: weighted gather-accumulate.
// No global atomics; ELU fused into the single output store.
__device__ __forceinline__ float lrelu(float x) {
    return (x > 0.0f) ? x : ALPHA * x;
}

__global__ __launch_bounds__(256)
void gat_node_kernel(float* __restrict__ out)
{
    const int n   = blockIdx.x;
    const int tid = threadIdx.x;
    const int beg = g_rowstart[n];
    const int end = g_rowstart[n + 1];

    __shared__ float s_red[4][8];
    __shared__ float s_m[4], s_inv[4];
    __shared__ float s_coef[64 * 4];
    __shared__ int   s_src[64];

    float4 a2v = reinterpret_cast<const float4*>(g_a2)[n];
    const float a2h[4] = {a2v.x, a2v.y, a2v.z, a2v.w};

    const int lane = tid & 31, warp = tid >> 5;

    // ---- Pass A: per-head segment max ----
    float m[4] = {-FLT_MAX, -FLT_MAX, -FLT_MAX, -FLT_MAX};
    for (int i = beg + tid; i < end; i += 256) {
        int s = g_csr_src[i];
        float4 a1v = reinterpret_cast<const float4*>(g_a1)[s];
        m[0] = fmaxf(m[0], lrelu(a1v.x + a2h[0]));
        m[1] = fmaxf(m[1], lrelu(a1v.y + a2h[1]));
        m[2] = fmaxf(m[2], lrelu(a1v.z + a2h[2]));
        m[3] = fmaxf(m[3], lrelu(a1v.w + a2h[3]));
    }
#pragma unroll
    for (int h = 0; h < 4; h++) {
#pragma unroll
        for (int o = 16; o > 0; o >>= 1)
            m[h] = fmaxf(m[h], __shfl_xor_sync(0xFFFFFFFFu, m[h], o));
        if (lane == 0) s_red[h][warp] = m[h];
    }
    __syncthreads();
    if (tid < 4) {
        float mm = s_red[tid][0];
#pragma unroll
        for (int w = 1; w < 8; w++) mm = fmaxf(mm, s_red[tid][w]);
        s_m[tid] = mm;
    }
    __syncthreads();

    // ---- Pass B: per-head segment sum of exp ----
    float sm[4] = {s_m[0], s_m[1], s_m[2], s_m[3]};
    float sum[4] = {0.f, 0.f, 0.f, 0.f};
    for (int i = beg + tid; i < end; i += 256) {
        int s = g_csr_src[i];
        float4 a1v = reinterpret_cast<const float4*>(g_a1)[s];
        sum[0] += __expf(lrelu(a1v.x + a2h[0]) - sm[0]);
        sum[1] += __expf(lrelu(a1v.y + a2h[1]) - sm[1]);
        sum[2] += __expf(lrelu(a1v.z + a2h[2]) - sm[2]);
        sum[3] += __expf(lrelu(a1v.w + a2h[3]) - sm[3]);
    }
#pragma unroll
    for (int h = 0; h < 4; h++) {
#pragma unroll
        for (int o = 16; o > 0; o >>= 1)
            sum[h] += __shfl_xor_sync(0xFFFFFFFFu, sum[h], o);
        if (lane == 0) s_red[h][warp] = sum[h];
    }
    __syncthreads();
    if (tid < 4) {
        float ss = 0.f;
#pragma unroll
        for (int w = 0; w < 8; w++) ss += s_red[tid][w];
        s_inv[tid] = 1.0f / ss;   // deg==0 -> never used
    }
    __syncthreads();

    // ---- Pass C: weighted gather-accumulate, tiled by 64 edges ----
    float acc = 0.0f;
    const int h = tid >> 6;                 // head of my feature column
    for (int t0 = beg; t0 < end; t0 += 64) {
        int cnt = min(64, end - t0);
        if (tid < cnt * 4) {
            int li = tid >> 2, hh = tid & 3;
            int s = g_csr_src[t0 + li];
            float x = lrelu(g_a1[s * 4 + hh] + a2h[hh]);
            s_coef[tid] = __expf(x - s_m[hh]) * s_inv[hh];
            if (hh == 0) s_src[li] = s;
        }
        __syncthreads();
#pragma unroll 4
        for (int li = 0; li < cnt; li++) {
            acc += s_coef[li * 4 + h] * g_ft[(size_t)s_src[li] * FDIM + tid];
        }
        __syncthreads();
    }

    // ---- fused ELU + store ----
    out[(size_t)n * FDIM + tid] = (acc > 0.0f) ? acc : expm1f(acc);
}

// ---------------- launch ------------------------------------------------------
extern "C" void kernel_launch(void* const* d_in, const int* in_sizes, int n_in,
                              void* d_out, int out_size)
{
    const float* feat   = (const float*)d_in[0];
    const int*   src    = (const int*)  d_in[1];
    const int*   dst    = (const int*)  d_in[2];
    const float* W      = (const float*)d_in[3];
    const float* attn_l = (const float*)d_in[4];
    const float* attn_r = (const float*)d_in[5];
    float* out = (float*)d_out;

    const int TPB = 256;

    init_kernel<<<(N_NODES + TPB - 1) / TPB, TPB>>>();

    {
        dim3 grid((N_NODES + BM - 1) / BM, FDIM / BN);
        gemm_kernel<<<grid, 256>>>(feat, W);
    }

    {
        int threads = N_NODES * HEADS * 32;
        a1a2_kernel<<<(threads + TPB - 1) / TPB, TPB>>>(attn_l, attn_r);
    }

    hist_kernel<<<(N_EDGES + TPB - 1) / TPB, TPB>>>(dst);
    scan1_kernel<<<SCAN_NB, SCAN_TPB>>>();
    scan2_kernel<<<1, SCAN_TPB>>>();
    scan3_kernel<<<SCAN_NB, SCAN_TPB>>>();
    scatter_kernel<<<(N_EDGES + TPB - 1) / TPB, TPB>>>(src, dst);

    gat_node_kernel<<<N_NODES, 256>>>(out);
}

// round 3
// speedup vs baseline: 1.5248x; 1.2597x over previous
#include <cuda_runtime.h>
#include <cuda_bf16.h>
#include <cstdint>
#include <cfloat>

#define N_NODES 50000
#define N_EDGES 800000
#define IN_DIM  256
#define HEADS   4
#define OUT_DIM 64
#define FDIM    256            // HEADS * OUT_DIM
#define ALPHA   0.2f

#define SCAN_TPB 256
#define SCAN_NB  ((N_NODES + SCAN_TPB - 1) / SCAN_TPB)   // 196

// ---------------- scratch (static device globals; no allocation) -------------
__device__ float g_ft [N_NODES * FDIM];      // projected features [N,256]
__device__ float g_a1 [N_NODES * HEADS];     // src-side attn term [N,4]
__device__ float g_a2 [N_NODES * HEADS];     // dst-side attn term [N,4]
__device__ int   g_deg     [N_NODES];        // in-degree histogram
__device__ int   g_rowstart[N_NODES + 1];    // CSR row offsets (by dst)
__device__ int   g_cursor  [N_NODES];        // scatter cursors
__device__ int   g_csr_src [N_EDGES];        // CSR payload: src node per slot
__device__ int   g_bsum [SCAN_NB];           // scan block sums
__device__ int   g_bscan[SCAN_NB];           // scanned block sums

// ---------------- 0) init ----------------------------------------------------
__global__ void init_kernel() {
    int i = blockIdx.x * blockDim.x + threadIdx.x;
    if (i < N_NODES) g_deg[i] = 0;
    if (i == 0) g_rowstart[N_NODES] = N_EDGES;
}

// ---------------- 1) GEMM via bf16 split-precision tensor cores --------------
// ft[m,n] = sum_k feat[m,k] * W[n,k]
// x = hi(x) + lo(x) (two bf16); D += Ah*Bh + Ah*Bl + Al*Bh (3 MMAs, lo*lo dropped)
#define GBM 128
#define GBN 128
#define GBK 32
#define LDT (GBK + 4)   // padded bf16 row stride (36)

__device__ __forceinline__ void split2(float a, float b,
                                       uint32_t& hi, uint32_t& lo) {
    __nv_bfloat16 ha = __float2bfloat16(a);
    __nv_bfloat16 hb = __float2bfloat16(b);
    __nv_bfloat162 hp; hp.x = ha; hp.y = hb;
    hi = reinterpret_cast<uint32_t&>(hp);
    __nv_bfloat162 lp;
    lp.x = __float2bfloat16(a - __bfloat162float(ha));
    lp.y = __float2bfloat16(b - __bfloat162float(hb));
    lo = reinterpret_cast<uint32_t&>(lp);
}

__device__ __forceinline__ void mma_bf16(float c[4],
                                         const uint32_t a[4],
                                         const uint32_t b0, const uint32_t b1) {
    asm volatile(
        "mma.sync.aligned.m16n8k16.row.col.f32.bf16.bf16.f32 "
        "{%0,%1,%2,%3}, {%4,%5,%6,%7}, {%8,%9}, {%0,%1,%2,%3};\n"
        : "+f"(c[0]), "+f"(c[1]), "+f"(c[2]), "+f"(c[3])
        : "r"(a[0]), "r"(a[1]), "r"(a[2]), "r"(a[3]), "r"(b0), "r"(b1));
}

__global__ __launch_bounds__(256)
void gemm_bf16x3_kernel(const float* __restrict__ A,   // [M,256] feat
                        const float* __restrict__ Wm)  // [256,256] W
{
    __shared__ __nv_bfloat16 Ah[GBM * LDT], Al[GBM * LDT];
    __shared__ __nv_bfloat16 Bh[GBN * LDT], Bl[GBN * LDT];

    const int tid  = threadIdx.x;
    const int warp = tid >> 5, lane = tid & 31;
    const int g = lane >> 2, t = lane & 3;
    const int warp_m = warp >> 1;          // 0..3
    const int warp_n = warp & 1;           // 0..1
    const int block_row = blockIdx.x * GBM;
    const int block_col = blockIdx.y * GBN;

    float acc[2][8][4];
#pragma unroll
    for (int mi = 0; mi < 2; mi++)
#pragma unroll
        for (int ni = 0; ni < 8; ni++)
#pragma unroll
            for (int i = 0; i < 4; i++) acc[mi][ni][i] = 0.0f;

    const int lrow = tid >> 1;             // 0..127
    const int lk0  = (tid & 1) * 16;       // 0 or 16

    for (int k0 = 0; k0 < IN_DIM; k0 += GBK) {
        // ---- load + split A tile [128 x 32] ----
        {
            int ar = block_row + lrow;
            bool ok = (ar < N_NODES);
#pragma unroll
            for (int q = 0; q < 4; q++) {
                int ko = lk0 + q * 4;
                float4 v = make_float4(0.f, 0.f, 0.f, 0.f);
                if (ok) v = *reinterpret_cast<const float4*>(
                                A + (size_t)ar * IN_DIM + k0 + ko);
                uint32_t h01, l01, h23, l23;
                split2(v.x, v.y, h01, l01);
                split2(v.z, v.w, h23, l23);
                *reinterpret_cast<uint32_t*>(&Ah[lrow * LDT + ko])     = h01;
                *reinterpret_cast<uint32_t*>(&Ah[lrow * LDT + ko + 2]) = h23;
                *reinterpret_cast<uint32_t*>(&Al[lrow * LDT + ko])     = l01;
                *reinterpret_cast<uint32_t*>(&Al[lrow * LDT + ko + 2]) = l23;
            }
        }
        // ---- load + split B tile from W (rows block_col..+127, always valid) ----
        {
            int br = block_col + lrow;
#pragma unroll
            for (int q = 0; q < 4; q++) {
                int ko = lk0 + q * 4;
                float4 v = *reinterpret_cast<const float4*>(
                               Wm + (size_t)br * IN_DIM + k0 + ko);
                uint32_t h01, l01, h23, l23;
                split2(v.x, v.y, h01, l01);
                split2(v.z, v.w, h23, l23);
                *reinterpret_cast<uint32_t*>(&Bh[lrow * LDT + ko])     = h01;
                *reinterpret_cast<uint32_t*>(&Bh[lrow * LDT + ko + 2]) = h23;
                *reinterpret_cast<uint32_t*>(&Bl[lrow * LDT + ko])     = l01;
                *reinterpret_cast<uint32_t*>(&Bl[lrow * LDT + ko + 2]) = l23;
            }
        }
        __syncthreads();

#pragma unroll
        for (int kk = 0; kk < GBK; kk += 16) {
            uint32_t ah[2][4], al[2][4];
#pragma unroll
            for (int mi = 0; mi < 2; mi++) {
                int mb = warp_m * 32 + mi * 16;
#pragma unroll
                for (int i = 0; i < 4; i++) {
                    int r = mb + g + (i & 1) * 8;
                    int c = kk + 2 * t + (i >> 1) * 8;
                    ah[mi][i] = *reinterpret_cast<uint32_t*>(&Ah[r * LDT + c]);
                    al[mi][i] = *reinterpret_cast<uint32_t*>(&Al[r * LDT + c]);
                }
            }
#pragma unroll
            for (int ni = 0; ni < 8; ni++) {
                int nb = warp_n * 64 + ni * 8 + g;
                uint32_t bh0, bh1, bl0, bl1;
                {
                    int c0 = kk + 2 * t, c1 = kk + 2 * t + 8;
                    bh0 = *reinterpret_cast<uint32_t*>(&Bh[nb * LDT + c0]);
                    bh1 = *reinterpret_cast<uint32_t*>(&Bh[nb * LDT + c1]);
                    bl0 = *reinterpret_cast<uint32_t*>(&Bl[nb * LDT + c0]);
                    bl1 = *reinterpret_cast<uint32_t*>(&Bl[nb * LDT + c1]);
                }
#pragma unroll
                for (int mi = 0; mi < 2; mi++) {
                    mma_bf16(acc[mi][ni], ah[mi], bh0, bh1);
                    mma_bf16(acc[mi][ni], ah[mi], bl0, bl1);
                    mma_bf16(acc[mi][ni], al[mi], bh0, bh1);
                }
            }
        }
        __syncthreads();
    }

    // ---- epilogue ----
#pragma unroll
    for (int mi = 0; mi < 2; mi++) {
#pragma unroll
        for (int ni = 0; ni < 8; ni++) {
            int row0 = block_row + warp_m * 32 + mi * 16 + g;
            int col  = block_col + warp_n * 64 + ni * 8 + 2 * t;
            if (row0 < N_NODES) {
                float2 v = make_float2(acc[mi][ni][0], acc[mi][ni][1]);
                *reinterpret_cast<float2*>(g_ft + (size_t)row0 * FDIM + col) = v;
            }
            int row1 = row0 + 8;
            if (row1 < N_NODES) {
                float2 v = make_float2(acc[mi][ni][2], acc[mi][ni][3]);
                *reinterpret_cast<float2*>(g_ft + (size_t)row1 * FDIM + col) = v;
            }
        }
    }
}

// ---------------- 2) per-node attention terms a1/a2 --------------------------
__global__ void a1a2_kernel(const float* __restrict__ attn_l,
                            const float* __restrict__ attn_r)
{
    int gtid = blockIdx.x * blockDim.x + threadIdx.x;
    int warp = gtid >> 5;
    int lane = gtid & 31;
    if (warp >= N_NODES * HEADS) return;
    int n = warp >> 2;
    int h = warp & 3;
    const float* row = g_ft + (size_t)n * FDIM + h * OUT_DIM;
    const float* al  = attn_l + h * OUT_DIM;
    const float* ar  = attn_r + h * OUT_DIM;
    float v0 = row[lane], v1 = row[lane + 32];
    float s1 = v0 * al[lane] + v1 * al[lane + 32];
    float s2 = v0 * ar[lane] + v1 * ar[lane + 32];
#pragma unroll
    for (int o = 16; o > 0; o >>= 1) {
        s1 += __shfl_xor_sync(0xFFFFFFFFu, s1, o);
        s2 += __shfl_xor_sync(0xFFFFFFFFu, s2, o);
    }
    if (lane == 0) {
        g_a1[n * HEADS + h] = s1;
        g_a2[n * HEADS + h] = s2;
    }
}

// ---------------- 3) CSR build: histogram, scan, scatter ---------------------
__global__ void hist_kernel(const int* __restrict__ dst) {
    int e = blockIdx.x * blockDim.x + threadIdx.x;
    if (e < N_EDGES) atomicAdd(&g_deg[dst[e]], 1);
}

__global__ __launch_bounds__(SCAN_TPB)
void scan1_kernel() {
    __shared__ int s[SCAN_TPB];
    int tid = threadIdx.x;
    int i = blockIdx.x * SCAN_TPB + tid;
    int v = (i < N_NODES) ? g_deg[i] : 0;
    s[tid] = v;
    __syncthreads();
#pragma unroll
    for (int off = 1; off < SCAN_TPB; off <<= 1) {
        int t = (tid >= off) ? s[tid - off] : 0;
        __syncthreads();
        s[tid] += t;
        __syncthreads();
    }
    if (i < N_NODES) g_rowstart[i] = s[tid] - v;
    if (tid == SCAN_TPB - 1) g_bsum[blockIdx.x] = s[tid];
}

__global__ __launch_bounds__(SCAN_TPB)
void scan2_kernel() {
    __shared__ int s[SCAN_TPB];
    int tid = threadIdx.x;
    int v = (tid < SCAN_NB) ? g_bsum[tid] : 0;
    s[tid] = v;
    __syncthreads();
#pragma unroll
    for (int off = 1; off < SCAN_TPB; off <<= 1) {
        int t = (tid >= off) ? s[tid - off] : 0;
        __syncthreads();
        s[tid] += t;
        __syncthreads();
    }
    if (tid < SCAN_NB) g_bscan[tid] = s[tid] - v;
}

__global__ __launch_bounds__(SCAN_TPB)
void scan3_kernel() {
    int i = blockIdx.x * SCAN_TPB + threadIdx.x;
    if (i < N_NODES) {
        int r = g_rowstart[i] + g_bscan[blockIdx.x];
        g_rowstart[i] = r;
        g_cursor[i] = r;
    }
}

__global__ void scatter_kernel(const int* __restrict__ src,
                               const int* __restrict__ dst) {
    int e = blockIdx.x * blockDim.x + threadIdx.x;
    if (e >= N_EDGES) return;
    int slot = atomicAdd(&g_cursor[dst[e]], 1);
    g_csr_src[slot] = src[e];
}

// ---------------- 4) fused per-dst-node GAT aggregation ----------------------
__device__ __forceinline__ float lrelu(float x) {
    return (x > 0.0f) ? x : ALPHA * x;
}

__global__ __launch_bounds__(256)
void gat_node_kernel(float* __restrict__ out)
{
    const int n   = blockIdx.x;
    const int tid = threadIdx.x;
    const int beg = g_rowstart[n];
    const int end = g_rowstart[n + 1];

    __shared__ float s_red[4][8];
    __shared__ float s_m[4], s_inv[4];
    __shared__ float s_coef[64 * 4];
    __shared__ int   s_src[64];

    float4 a2v = reinterpret_cast<const float4*>(g_a2)[n];
    const float a2h[4] = {a2v.x, a2v.y, a2v.z, a2v.w};

    const int lane = tid & 31, warp = tid >> 5;

    // ---- Pass A: per-head segment max ----
    float m[4] = {-FLT_MAX, -FLT_MAX, -FLT_MAX, -FLT_MAX};
    for (int i = beg + tid; i < end; i += 256) {
        int s = g_csr_src[i];
        float4 a1v = reinterpret_cast<const float4*>(g_a1)[s];
        m[0] = fmaxf(m[0], lrelu(a1v.x + a2h[0]));
        m[1] = fmaxf(m[1], lrelu(a1v.y + a2h[1]));
        m[2] = fmaxf(m[2], lrelu(a1v.z + a2h[2]));
        m[3] = fmaxf(m[3], lrelu(a1v.w + a2h[3]));
    }
#pragma unroll
    for (int h = 0; h < 4; h++) {
#pragma unroll
        for (int o = 16; o > 0; o >>= 1)
            m[h] = fmaxf(m[h], __shfl_xor_sync(0xFFFFFFFFu, m[h], o));
        if (lane == 0) s_red[h][warp] = m[h];
    }
    __syncthreads();
    if (tid < 4) {
        float mm = s_red[tid][0];
#pragma unroll
        for (int w = 1; w < 8; w++) mm = fmaxf(mm, s_red[tid][w]);
        s_m[tid] = mm;
    }
    __syncthreads();

    // ---- Pass B: per-head segment sum of exp ----
    float sm[4] = {s_m[0], s_m[1], s_m[2], s_m[3]};
    float sum[4] = {0.f, 0.f, 0.f, 0.f};
    for (int i = beg + tid; i < end; i += 256) {
        int s = g_csr_src[i];
        float4 a1v = reinterpret_cast<const float4*>(g_a1)[s];
        sum[0] += __expf(lrelu(a1v.x + a2h[0]) - sm[0]);
        sum[1] += __expf(lrelu(a1v.y + a2h[1]) - sm[1]);
        sum[2] += __expf(lrelu(a1v.z + a2h[2]) - sm[2]);
        sum[3] += __expf(lrelu(a1v.w + a2h[3]) - sm[3]);
    }
#pragma unroll
    for (int h = 0; h < 4; h++) {
#pragma unroll
        for (int o = 16; o > 0; o >>= 1)
            sum[h] += __shfl_xor_sync(0xFFFFFFFFu, sum[h], o);
        if (lane == 0) s_red[h][warp] = sum[h];
    }
    __syncthreads();
    if (tid < 4) {
        float ss = 0.f;
#pragma unroll
        for (int w = 0; w < 8; w++) ss += s_red[tid][w];
        s_inv[tid] = 1.0f / ss;
    }
    __syncthreads();

    // ---- Pass C: weighted gather-accumulate, tiled by 64 edges ----
    float acc = 0.0f;
    const int h = tid >> 6;
    for (int t0 = beg; t0 < end; t0 += 64) {
        int cnt = min(64, end - t0);
        if (tid < cnt * 4) {
            int li = tid >> 2, hh = tid & 3;
            int s = g_csr_src[t0 + li];
            float x = lrelu(g_a1[s * 4 + hh] + a2h[hh]);
            s_coef[tid] = __expf(x - s_m[hh]) * s_inv[hh];
            if (hh == 0) s_src[li] = s;
        }
        __syncthreads();
#pragma unroll 4
        for (int li = 0; li < cnt; li++) {
            acc += s_coef[li * 4 + h] * g_ft[(size_t)s_src[li] * FDIM + tid];
        }
        __syncthreads();
    }

    out[(size_t)n * FDIM + tid] = (acc > 0.0f) ? acc : expm1f(acc);
}

// ---------------- launch ------------------------------------------------------
extern "C" void kernel_launch(void* const* d_in, const int* in_sizes, int n_in,
                              void* d_out, int out_size)
{
    const float* feat   = (const float*)d_in[0];
    const int*   src    = (const int*)  d_in[1];
    const int*   dst    = (const int*)  d_in[2];
    const float* W      = (const float*)d_in[3];
    const float* attn_l = (const float*)d_in[4];
    const float* attn_r = (const float*)d_in[5];
    float* out = (float*)d_out;

    const int TPB = 256;

    init_kernel<<<(N_NODES + TPB - 1) / TPB, TPB>>>();

    {
        dim3 grid((N_NODES + GBM - 1) / GBM, FDIM / GBN);
        gemm_bf16x3_kernel<<<grid, 256>>>(feat, W);
    }

    {
        int threads = N_NODES * HEADS * 32;
        a1a2_kernel<<<(threads + TPB - 1) / TPB, TPB>>>(attn_l, attn_r);
    }

    hist_kernel<<<(N_EDGES + TPB - 1) / TPB, TPB>>>(dst);
    scan1_kernel<<<SCAN_NB, SCAN_TPB>>>();
    scan2_kernel<<<1, SCAN_TPB>>>();
    scan3_kernel<<<SCAN_NB, SCAN_TPB>>>();
    scatter_kernel<<<(N_EDGES + TPB - 1) / TPB, TPB>>>(src, dst);

    gat_node_kernel<<<N_NODES, 256>>>(out);
}

// round 4
// speedup vs baseline: 2.4648x; 1.6165x over previous
#include <cuda_runtime.h>
#include <cuda_bf16.h>
#include <cstdint>
#include <cfloat>

#define N_NODES 50000
#define N_EDGES 800000
#define IN_DIM  256
#define HEADS   4
#define OUT_DIM 64
#define FDIM    256            // HEADS * OUT_DIM
#define ALPHA   0.2f

#define SCAN_TPB 256
#define SCAN_NB  ((N_NODES + SCAN_TPB - 1) / SCAN_TPB)   // 196

// ---------------- scratch (static device globals; no allocation) -------------
__device__ float g_ft [N_NODES * FDIM];      // projected features [N,256]
__device__ float g_a1 [N_NODES * HEADS];     // src-side attn term [N,4]
__device__ float g_a2 [N_NODES * HEADS];     // dst-side attn term [N,4]
__device__ int   g_deg     [N_NODES];        // in-degree histogram
__device__ int   g_rowstart[N_NODES + 1];    // CSR row offsets (by dst)
__device__ int   g_cursor  [N_NODES];        // scatter cursors
__device__ int   g_csr_src [N_EDGES];        // CSR payload: src node per slot
__device__ int   g_bsum [SCAN_NB];           // scan block sums
__device__ int   g_bscan[SCAN_NB];           // scanned block sums

// ---------------- 0) init ----------------------------------------------------
__global__ void init_kernel() {
    int i = blockIdx.x * blockDim.x + threadIdx.x;
    if (i < N_NODES) g_deg[i] = 0;
    if (i == 0) g_rowstart[N_NODES] = N_EDGES;
}

// ---------------- 1) GEMM via bf16 split-precision tensor cores --------------
#define GBM 128
#define GBN 128
#define GBK 32
#define LDT (GBK + 4)

__device__ __forceinline__ void split2(float a, float b,
                                       uint32_t& hi, uint32_t& lo) {
    __nv_bfloat16 ha = __float2bfloat16(a);
    __nv_bfloat16 hb = __float2bfloat16(b);
    __nv_bfloat162 hp; hp.x = ha; hp.y = hb;
    hi = reinterpret_cast<uint32_t&>(hp);
    __nv_bfloat162 lp;
    lp.x = __float2bfloat16(a - __bfloat162float(ha));
    lp.y = __float2bfloat16(b - __bfloat162float(hb));
    lo = reinterpret_cast<uint32_t&>(lp);
}

__device__ __forceinline__ void mma_bf16(float c[4],
                                         const uint32_t a[4],
                                         const uint32_t b0, const uint32_t b1) {
    asm volatile(
        "mma.sync.aligned.m16n8k16.row.col.f32.bf16.bf16.f32 "
        "{%0,%1,%2,%3}, {%4,%5,%6,%7}, {%8,%9}, {%0,%1,%2,%3};\n"
        : "+f"(c[0]), "+f"(c[1]), "+f"(c[2]), "+f"(c[3])
        : "r"(a[0]), "r"(a[1]), "r"(a[2]), "r"(a[3]), "r"(b0), "r"(b1));
}

__global__ __launch_bounds__(256)
void gemm_bf16x3_kernel(const float* __restrict__ A,
                        const float* __restrict__ Wm)
{
    __shared__ __nv_bfloat16 Ah[GBM * LDT], Al[GBM * LDT];
    __shared__ __nv_bfloat16 Bh[GBN * LDT], Bl[GBN * LDT];

    const int tid  = threadIdx.x;
    const int warp = tid >> 5, lane = tid & 31;
    const int g = lane >> 2, t = lane & 3;
    const int warp_m = warp >> 1;
    const int warp_n = warp & 1;
    const int block_row = blockIdx.x * GBM;
    const int block_col = blockIdx.y * GBN;

    float acc[2][8][4];
#pragma unroll
    for (int mi = 0; mi < 2; mi++)
#pragma unroll
        for (int ni = 0; ni < 8; ni++)
#pragma unroll
            for (int i = 0; i < 4; i++) acc[mi][ni][i] = 0.0f;

    const int lrow = tid >> 1;
    const int lk0  = (tid & 1) * 16;

    for (int k0 = 0; k0 < IN_DIM; k0 += GBK) {
        {
            int ar = block_row + lrow;
            bool ok = (ar < N_NODES);
#pragma unroll
            for (int q = 0; q < 4; q++) {
                int ko = lk0 + q * 4;
                float4 v = make_float4(0.f, 0.f, 0.f, 0.f);
                if (ok) v = *reinterpret_cast<const float4*>(
                                A + (size_t)ar * IN_DIM + k0 + ko);
                uint32_t h01, l01, h23, l23;
                split2(v.x, v.y, h01, l01);
                split2(v.z, v.w, h23, l23);
                *reinterpret_cast<uint32_t*>(&Ah[lrow * LDT + ko])     = h01;
                *reinterpret_cast<uint32_t*>(&Ah[lrow * LDT + ko + 2]) = h23;
                *reinterpret_cast<uint32_t*>(&Al[lrow * LDT + ko])     = l01;
                *reinterpret_cast<uint32_t*>(&Al[lrow * LDT + ko + 2]) = l23;
            }
        }
        {
            int br = block_col + lrow;
#pragma unroll
            for (int q = 0; q < 4; q++) {
                int ko = lk0 + q * 4;
                float4 v = *reinterpret_cast<const float4*>(
                               Wm + (size_t)br * IN_DIM + k0 + ko);
                uint32_t h01, l01, h23, l23;
                split2(v.x, v.y, h01, l01);
                split2(v.z, v.w, h23, l23);
                *reinterpret_cast<uint32_t*>(&Bh[lrow * LDT + ko])     = h01;
                *reinterpret_cast<uint32_t*>(&Bh[lrow * LDT + ko + 2]) = h23;
                *reinterpret_cast<uint32_t*>(&Bl[lrow * LDT + ko])     = l01;
                *reinterpret_cast<uint32_t*>(&Bl[lrow * LDT + ko + 2]) = l23;
            }
        }
        __syncthreads();

#pragma unroll
        for (int kk = 0; kk < GBK; kk += 16) {
            uint32_t ah[2][4], al[2][4];
#pragma unroll
            for (int mi = 0; mi < 2; mi++) {
                int mb = warp_m * 32 + mi * 16;
#pragma unroll
                for (int i = 0; i < 4; i++) {
                    int r = mb + g + (i & 1) * 8;
                    int c = kk + 2 * t + (i >> 1) * 8;
                    ah[mi][i] = *reinterpret_cast<uint32_t*>(&Ah[r * LDT + c]);
                    al[mi][i] = *reinterpret_cast<uint32_t*>(&Al[r * LDT + c]);
                }
            }
#pragma unroll
            for (int ni = 0; ni < 8; ni++) {
                int nb = warp_n * 64 + ni * 8 + g;
                uint32_t bh0, bh1, bl0, bl1;
                {
                    int c0 = kk + 2 * t, c1 = kk + 2 * t + 8;
                    bh0 = *reinterpret_cast<uint32_t*>(&Bh[nb * LDT + c0]);
                    bh1 = *reinterpret_cast<uint32_t*>(&Bh[nb * LDT + c1]);
                    bl0 = *reinterpret_cast<uint32_t*>(&Bl[nb * LDT + c0]);
                    bl1 = *reinterpret_cast<uint32_t*>(&Bl[nb * LDT + c1]);
                }
#pragma unroll
                for (int mi = 0; mi < 2; mi++) {
                    mma_bf16(acc[mi][ni], ah[mi], bh0, bh1);
                    mma_bf16(acc[mi][ni], ah[mi], bl0, bl1);
                    mma_bf16(acc[mi][ni], al[mi], bh0, bh1);
                }
            }
        }
        __syncthreads();
    }

#pragma unroll
    for (int mi = 0; mi < 2; mi++) {
#pragma unroll
        for (int ni = 0; ni < 8; ni++) {
            int row0 = block_row + warp_m * 32 + mi * 16 + g;
            int col  = block_col + warp_n * 64 + ni * 8 + 2 * t;
            if (row0 < N_NODES) {
                *reinterpret_cast<float2*>(g_ft + (size_t)row0 * FDIM + col) =
                    make_float2(acc[mi][ni][0], acc[mi][ni][1]);
            }
            int row1 = row0 + 8;
            if (row1 < N_NODES) {
                *reinterpret_cast<float2*>(g_ft + (size_t)row1 * FDIM + col) =
                    make_float2(acc[mi][ni][2], acc[mi][ni][3]);
            }
        }
    }
}

// ---------------- 2) per-node attention terms a1/a2 --------------------------
__global__ void a1a2_kernel(const float* __restrict__ attn_l,
                            const float* __restrict__ attn_r)
{
    int gtid = blockIdx.x * blockDim.x + threadIdx.x;
    int warp = gtid >> 5;
    int lane = gtid & 31;
    if (warp >= N_NODES * HEADS) return;
    int n = warp >> 2;
    int h = warp & 3;
    const float* row = g_ft + (size_t)n * FDIM + h * OUT_DIM;
    const float* al  = attn_l + h * OUT_DIM;
    const float* ar  = attn_r + h * OUT_DIM;
    float v0 = row[lane], v1 = row[lane + 32];
    float s1 = v0 * al[lane] + v1 * al[lane + 32];
    float s2 = v0 * ar[lane] + v1 * ar[lane + 32];
#pragma unroll
    for (int o = 16; o > 0; o >>= 1) {
        s1 += __shfl_xor_sync(0xFFFFFFFFu, s1, o);
        s2 += __shfl_xor_sync(0xFFFFFFFFu, s2, o);
    }
    if (lane == 0) {
        g_a1[n * HEADS + h] = s1;
        g_a2[n * HEADS + h] = s2;
    }
}

// ---------------- 3) CSR build: histogram, scan, scatter ---------------------
__global__ void hist_kernel(const int* __restrict__ dst) {
    int e = blockIdx.x * blockDim.x + threadIdx.x;
    if (e < N_EDGES) atomicAdd(&g_deg[dst[e]], 1);
}

__global__ __launch_bounds__(SCAN_TPB)
void scan1_kernel() {
    __shared__ int s[SCAN_TPB];
    int tid = threadIdx.x;
    int i = blockIdx.x * SCAN_TPB + tid;
    int v = (i < N_NODES) ? g_deg[i] : 0;
    s[tid] = v;
    __syncthreads();
#pragma unroll
    for (int off = 1; off < SCAN_TPB; off <<= 1) {
        int t = (tid >= off) ? s[tid - off] : 0;
        __syncthreads();
        s[tid] += t;
        __syncthreads();
    }
    if (i < N_NODES) g_rowstart[i] = s[tid] - v;
    if (tid == SCAN_TPB - 1) g_bsum[blockIdx.x] = s[tid];
}

__global__ __launch_bounds__(SCAN_TPB)
void scan2_kernel() {
    __shared__ int s[SCAN_TPB];
    int tid = threadIdx.x;
    int v = (tid < SCAN_NB) ? g_bsum[tid] : 0;
    s[tid] = v;
    __syncthreads();
#pragma unroll
    for (int off = 1; off < SCAN_TPB; off <<= 1) {
        int t = (tid >= off) ? s[tid - off] : 0;
        __syncthreads();
        s[tid] += t;
        __syncthreads();
    }
    if (tid < SCAN_NB) g_bscan[tid] = s[tid] - v;
}

__global__ __launch_bounds__(SCAN_TPB)
void scan3_kernel() {
    int i = blockIdx.x * SCAN_TPB + threadIdx.x;
    if (i < N_NODES) {
        int r = g_rowstart[i] + g_bscan[blockIdx.x];
        g_rowstart[i] = r;
        g_cursor[i] = r;
    }
}

__global__ void scatter_kernel(const int* __restrict__ src,
                               const int* __restrict__ dst) {
    int e = blockIdx.x * blockDim.x + threadIdx.x;
    if (e >= N_EDGES) return;
    int slot = atomicAdd(&g_cursor[dst[e]], 1);
    g_csr_src[slot] = src[e];
}

// ---------------- 4) warp-per-node fused GAT aggregation ---------------------
__device__ __forceinline__ float lrelu(float x) {
    return (x > 0.0f) ? x : ALPHA * x;
}
__device__ __forceinline__ float wred_max(float v) {
#pragma unroll
    for (int o = 16; o > 0; o >>= 1)
        v = fmaxf(v, __shfl_xor_sync(0xFFFFFFFFu, v, o));
    return v;
}
__device__ __forceinline__ float wred_sum(float v) {
#pragma unroll
    for (int o = 16; o > 0; o >>= 1)
        v += __shfl_xor_sync(0xFFFFFFFFu, v, o);
    return v;
}

#define GAT_WPB 8   // warps per block

__global__ __launch_bounds__(GAT_WPB * 32)
void gat_warp_kernel(float* __restrict__ out)
{
    const int wid  = threadIdx.x >> 5;
    const int lane = threadIdx.x & 31;
    const int n    = blockIdx.x * GAT_WPB + wid;   // 50000 = 6250*8, exact

    __shared__ float4 s_coef[GAT_WPB][32];
    __shared__ int    s_srcs[GAT_WPB][32];

    const int beg = g_rowstart[n];
    const int end = g_rowstart[n + 1];
    const int deg = end - beg;

    float4 a2v = __ldg(&reinterpret_cast<const float4*>(g_a2)[n]);

    float4 acc0 = make_float4(0.f, 0.f, 0.f, 0.f);
    float4 acc1 = make_float4(0.f, 0.f, 0.f, 0.f);
    const int h0 = lane >> 4;        // head for cols [lane*4)      in 0..127
    const int h1 = h0 + 2;           // head for cols [128+lane*4)

    if (deg <= 32) {
        // ---------- fast path: lane i owns edge i, scores in registers ----------
        int   s  = 0;
        float x0 = -FLT_MAX, x1 = -FLT_MAX, x2 = -FLT_MAX, x3 = -FLT_MAX;
        if (lane < deg) {
            s = __ldg(&g_csr_src[beg + lane]);
            float4 a1v = __ldg(&reinterpret_cast<const float4*>(g_a1)[s]);
            x0 = lrelu(a1v.x + a2v.x);
            x1 = lrelu(a1v.y + a2v.y);
            x2 = lrelu(a1v.z + a2v.z);
            x3 = lrelu(a1v.w + a2v.w);
        }
        float m0 = wred_max(x0), m1 = wred_max(x1);
        float m2 = wred_max(x2), m3 = wred_max(x3);
        float e0 = 0.f, e1 = 0.f, e2 = 0.f, e3 = 0.f;
        if (lane < deg) {
            e0 = __expf(x0 - m0); e1 = __expf(x1 - m1);
            e2 = __expf(x2 - m2); e3 = __expf(x3 - m3);
        }
        float i0 = 1.0f / wred_sum(e0), i1 = 1.0f / wred_sum(e1);
        float i2 = 1.0f / wred_sum(e2), i3 = 1.0f / wred_sum(e3);
        if (lane < deg) {
            s_coef[wid][lane] = make_float4(e0 * i0, e1 * i1, e2 * i2, e3 * i3);
            s_srcs[wid][lane] = s;
        }
        __syncwarp();

        const float* cf = reinterpret_cast<const float*>(&s_coef[wid][0]);
        int li = 0;
        for (; li + 2 <= deg; li += 2) {
            int sa = s_srcs[wid][li], sb = s_srcs[wid][li + 1];
            const float4* ra = reinterpret_cast<const float4*>(
                                   g_ft + (size_t)sa * FDIM) + lane;
            const float4* rb = reinterpret_cast<const float4*>(
                                   g_ft + (size_t)sb * FDIM) + lane;
            float4 va0 = __ldg(ra), va1 = __ldg(ra + 32);
            float4 vb0 = __ldg(rb), vb1 = __ldg(rb + 32);
            float ca0 = cf[li * 4 + h0],     ca1 = cf[li * 4 + h1];
            float cb0 = cf[li * 4 + 4 + h0], cb1 = cf[li * 4 + 4 + h1];
            acc0.x += ca0 * va0.x + cb0 * vb0.x;
            acc0.y += ca0 * va0.y + cb0 * vb0.y;
            acc0.z += ca0 * va0.z + cb0 * vb0.z;
            acc0.w += ca0 * va0.w + cb0 * vb0.w;
            acc1.x += ca1 * va1.x + cb1 * vb1.x;
            acc1.y += ca1 * va1.y + cb1 * vb1.y;
            acc1.z += ca1 * va1.z + cb1 * vb1.z;
            acc1.w += ca1 * va1.w + cb1 * vb1.w;
        }
        if (li < deg) {
            int sa = s_srcs[wid][li];
            const float4* ra = reinterpret_cast<const float4*>(
                                   g_ft + (size_t)sa * FDIM) + lane;
            float4 va0 = __ldg(ra), va1 = __ldg(ra + 32);
            float ca0 = cf[li * 4 + h0], ca1 = cf[li * 4 + h1];
            acc0.x += ca0 * va0.x; acc0.y += ca0 * va0.y;
            acc0.z += ca0 * va0.z; acc0.w += ca0 * va0.w;
            acc1.x += ca1 * va1.x; acc1.y += ca1 * va1.y;
            acc1.z += ca1 * va1.z; acc1.w += ca1 * va1.w;
        }
    } else {
        // ---------- slow path: generic strided 2-pass + 32-edge tiles ----------
        float m0 = -FLT_MAX, m1 = -FLT_MAX, m2 = -FLT_MAX, m3 = -FLT_MAX;
        for (int i = beg + lane; i < end; i += 32) {
            int s = g_csr_src[i];
            float4 a1v = __ldg(&reinterpret_cast<const float4*>(g_a1)[s]);
            m0 = fmaxf(m0, lrelu(a1v.x + a2v.x));
            m1 = fmaxf(m1, lrelu(a1v.y + a2v.y));
            m2 = fmaxf(m2, lrelu(a1v.z + a2v.z));
            m3 = fmaxf(m3, lrelu(a1v.w + a2v.w));
        }
        m0 = wred_max(m0); m1 = wred_max(m1);
        m2 = wred_max(m2); m3 = wred_max(m3);
        float t0 = 0.f, t1 = 0.f, t2 = 0.f, t3 = 0.f;
        for (int i = beg + lane; i < end; i += 32) {
            int s = g_csr_src[i];
            float4 a1v = __ldg(&reinterpret_cast<const float4*>(g_a1)[s]);
            t0 += __expf(lrelu(a1v.x + a2v.x) - m0);
            t1 += __expf(lrelu(a1v.y + a2v.y) - m1);
            t2 += __expf(lrelu(a1v.z + a2v.z) - m2);
            t3 += __expf(lrelu(a1v.w + a2v.w) - m3);
        }
        float i0 = 1.0f / wred_sum(t0), i1 = 1.0f / wred_sum(t1);
        float i2 = 1.0f / wred_sum(t2), i3 = 1.0f / wred_sum(t3);

        const float* cf = reinterpret_cast<const float*>(&s_coef[wid][0]);
        for (int tb = beg; tb < end; tb += 32) {
            int cnt = min(32, end - tb);
            if (lane < cnt) {
                int s = __ldg(&g_csr_src[tb + lane]);
                float4 a1v = __ldg(&reinterpret_cast<const float4*>(g_a1)[s]);
                s_coef[wid][lane] = make_float4(
                    __expf(lrelu(a1v.x + a2v.x) - m0) * i0,
                    __expf(lrelu(a1v.y + a2v.y) - m1) * i1,
                    __expf(lrelu(a1v.z + a2v.z) - m2) * i2,
                    __expf(lrelu(a1v.w + a2v.w) - m3) * i3);
                s_srcs[wid][lane] = s;
            }
            __syncwarp();
            for (int li = 0; li < cnt; li++) {
                int sa = s_srcs[wid][li];
                const float4* ra = reinterpret_cast<const float4*>(
                                       g_ft + (size_t)sa * FDIM) + lane;
                float4 va0 = __ldg(ra), va1 = __ldg(ra + 32);
                float ca0 = cf[li * 4 + h0], ca1 = cf[li * 4 + h1];
                acc0.x += ca0 * va0.x; acc0.y += ca0 * va0.y;
                acc0.z += ca0 * va0.z; acc0.w += ca0 * va0.w;
                acc1.x += ca1 * va1.x; acc1.y += ca1 * va1.y;
                acc1.z += ca1 * va1.z; acc1.w += ca1 * va1.w;
            }
            __syncwarp();
        }
    }

    // ---- fused ELU + store ----
    float4 o0 = make_float4(
        acc0.x > 0.f ? acc0.x : expm1f(acc0.x),
        acc0.y > 0.f ? acc0.y : expm1f(acc0.y),
        acc0.z > 0.f ? acc0.z : expm1f(acc0.z),
        acc0.w > 0.f ? acc0.w : expm1f(acc0.w));
    float4 o1 = make_float4(
        acc1.x > 0.f ? acc1.x : expm1f(acc1.x),
        acc1.y > 0.f ? acc1.y : expm1f(acc1.y),
        acc1.z > 0.f ? acc1.z : expm1f(acc1.z),
        acc1.w > 0.f ? acc1.w : expm1f(acc1.w));
    float4* orow = reinterpret_cast<float4*>(out + (size_t)n * FDIM) + lane;
    orow[0]  = o0;
    orow[32] = o1;
}

// ---------------- launch ------------------------------------------------------
extern "C" void kernel_launch(void* const* d_in, const int* in_sizes, int n_in,
                              void* d_out, int out_size)
{
    const float* feat   = (const float*)d_in[0];
    const int*   src    = (const int*)  d_in[1];
    const int*   dst    = (const int*)  d_in[2];
    const float* W      = (const float*)d_in[3];
    const float* attn_l = (const float*)d_in[4];
    const float* attn_r = (const float*)d_in[5];
    float* out = (float*)d_out;

    const int TPB = 256;

    init_kernel<<<(N_NODES + TPB - 1) / TPB, TPB>>>();

    {
        dim3 grid((N_NODES + GBM - 1) / GBM, FDIM / GBN);
        gemm_bf16x3_kernel<<<grid, 256>>>(feat, W);
    }

    {
        int threads = N_NODES * HEADS * 32;
        a1a2_kernel<<<(threads + TPB - 1) / TPB, TPB>>>(attn_l, attn_r);
    }

    hist_kernel<<<(N_EDGES + TPB - 1) / TPB, TPB>>>(dst);
    scan1_kernel<<<SCAN_NB, SCAN_TPB>>>();
    scan2_kernel<<<1, SCAN_TPB>>>();
    scan3_kernel<<<SCAN_NB, SCAN_TPB>>>();
    scatter_kernel<<<(N_EDGES + TPB - 1) / TPB, TPB>>>(src, dst);

    gat_warp_kernel<<<N_NODES / GAT_WPB, GAT_WPB * 32>>>(out);
}

// round 5
// speedup vs baseline: 2.5385x; 1.0299x over previous
#include <cuda_runtime.h>
#include <cuda_bf16.h>
#include <cstdint>
#include <cfloat>

#define N_NODES 50000
#define N_EDGES 800000
#define IN_DIM  256
#define HEADS   4
#define OUT_DIM 64
#define FDIM    256            // HEADS * OUT_DIM
#define ALPHA   0.2f

#define SCAN_TPB 256
#define SCAN_NB  ((N_NODES + SCAN_TPB - 1) / SCAN_TPB)   // 196

// ---------------- scratch (static device globals; no allocation) -------------
__device__ float g_ft [N_NODES * FDIM];      // projected features [N,256]
__device__ float g_a1 [N_NODES * HEADS];     // src-side attn term [N,4]
__device__ float g_a2 [N_NODES * HEADS];     // dst-side attn term [N,4]
__device__ int   g_deg     [N_NODES];        // in-degree histogram
__device__ int   g_rowstart[N_NODES + 1];    // CSR row offsets (by dst)
__device__ int   g_cursor  [N_NODES];        // scatter cursors
__device__ int   g_csr_src [N_EDGES];        // CSR payload: src node per slot
__device__ int   g_bsum [SCAN_NB];           // scan block sums
__device__ int   g_bscan[SCAN_NB];           // scanned block sums

// ---------------- 0) init ----------------------------------------------------
__global__ void init_kernel() {
    int i = blockIdx.x * blockDim.x + threadIdx.x;
    if (i < N_NODES) g_deg[i] = 0;
    if (i == 0) g_rowstart[N_NODES] = N_EDGES;
}

// ---------------- 1) GEMM via bf16 split-precision tensor cores --------------
// double-buffered: next tile's global loads issued before consuming current smem
#define GBM 128
#define GBN 128
#define GBK 32
#define LDT (GBK + 4)

__device__ __forceinline__ void split2(float a, float b,
                                       uint32_t& hi, uint32_t& lo) {
    __nv_bfloat16 ha = __float2bfloat16(a);
    __nv_bfloat16 hb = __float2bfloat16(b);
    __nv_bfloat162 hp; hp.x = ha; hp.y = hb;
    hi = reinterpret_cast<uint32_t&>(hp);
    __nv_bfloat162 lp;
    lp.x = __float2bfloat16(a - __bfloat162float(ha));
    lp.y = __float2bfloat16(b - __bfloat162float(hb));
    lo = reinterpret_cast<uint32_t&>(lp);
}

__device__ __forceinline__ void mma_bf16(float c[4],
                                         const uint32_t a[4],
                                         const uint32_t b0, const uint32_t b1) {
    asm volatile(
        "mma.sync.aligned.m16n8k16.row.col.f32.bf16.bf16.f32 "
        "{%0,%1,%2,%3}, {%4,%5,%6,%7}, {%8,%9}, {%0,%1,%2,%3};\n"
        : "+f"(c[0]), "+f"(c[1]), "+f"(c[2]), "+f"(c[3])
        : "r"(a[0]), "r"(a[1]), "r"(a[2]), "r"(a[3]), "r"(b0), "r"(b1));
}

__global__ __launch_bounds__(256)
void gemm_bf16x3_kernel(const float* __restrict__ A,
                        const float* __restrict__ Wm)
{
    __shared__ __nv_bfloat16 Ah[GBM * LDT], Al[GBM * LDT];
    __shared__ __nv_bfloat16 Bh[GBN * LDT], Bl[GBN * LDT];

    const int tid  = threadIdx.x;
    const int warp = tid >> 5, lane = tid & 31;
    const int g = lane >> 2, t = lane & 3;
    const int warp_m = warp >> 1;
    const int warp_n = warp & 1;
    const int block_row = blockIdx.x * GBM;
    const int block_col = blockIdx.y * GBN;

    float acc[2][8][4];
#pragma unroll
    for (int mi = 0; mi < 2; mi++)
#pragma unroll
        for (int ni = 0; ni < 8; ni++)
#pragma unroll
            for (int i = 0; i < 4; i++) acc[mi][ni][i] = 0.0f;

    const int lrow = tid >> 1;
    const int lk0  = (tid & 1) * 16;
    const int ar   = block_row + lrow;
    const bool aok = (ar < N_NODES);
    const int br   = block_col + lrow;

    float4 pa[4], pb[4];
    // initial prefetch (k0 = 0)
#pragma unroll
    for (int q = 0; q < 4; q++) {
        int ko = lk0 + q * 4;
        pa[q] = aok ? *reinterpret_cast<const float4*>(A + (size_t)ar * IN_DIM + ko)
                    : make_float4(0.f, 0.f, 0.f, 0.f);
        pb[q] = *reinterpret_cast<const float4*>(Wm + (size_t)br * IN_DIM + ko);
    }

    for (int k0 = 0; k0 < IN_DIM; k0 += GBK) {
        // ---- split current prefetched tile into smem ----
#pragma unroll
        for (int q = 0; q < 4; q++) {
            int ko = lk0 + q * 4;
            uint32_t h01, l01, h23, l23;
            split2(pa[q].x, pa[q].y, h01, l01);
            split2(pa[q].z, pa[q].w, h23, l23);
            *reinterpret_cast<uint32_t*>(&Ah[lrow * LDT + ko])     = h01;
            *reinterpret_cast<uint32_t*>(&Ah[lrow * LDT + ko + 2]) = h23;
            *reinterpret_cast<uint32_t*>(&Al[lrow * LDT + ko])     = l01;
            *reinterpret_cast<uint32_t*>(&Al[lrow * LDT + ko + 2]) = l23;
            split2(pb[q].x, pb[q].y, h01, l01);
            split2(pb[q].z, pb[q].w, h23, l23);
            *reinterpret_cast<uint32_t*>(&Bh[lrow * LDT + ko])     = h01;
            *reinterpret_cast<uint32_t*>(&Bh[lrow * LDT + ko + 2]) = h23;
            *reinterpret_cast<uint32_t*>(&Bl[lrow * LDT + ko])     = l01;
            *reinterpret_cast<uint32_t*>(&Bl[lrow * LDT + ko + 2]) = l23;
        }
        __syncthreads();

        // ---- prefetch next tile (overlaps with MMA compute below) ----
        int kn = k0 + GBK;
        if (kn < IN_DIM) {
#pragma unroll
            for (int q = 0; q < 4; q++) {
                int ko = kn + lk0 + q * 4;
                pa[q] = aok ? *reinterpret_cast<const float4*>(
                                  A + (size_t)ar * IN_DIM + ko)
                            : make_float4(0.f, 0.f, 0.f, 0.f);
                pb[q] = *reinterpret_cast<const float4*>(
                            Wm + (size_t)br * IN_DIM + ko);
            }
        }

        // ---- MMA compute on current smem tile ----
#pragma unroll
        for (int kk = 0; kk < GBK; kk += 16) {
            uint32_t ah[2][4], al[2][4];
#pragma unroll
            for (int mi = 0; mi < 2; mi++) {
                int mb = warp_m * 32 + mi * 16;
#pragma unroll
                for (int i = 0; i < 4; i++) {
                    int r = mb + g + (i & 1) * 8;
                    int c = kk + 2 * t + (i >> 1) * 8;
                    ah[mi][i] = *reinterpret_cast<uint32_t*>(&Ah[r * LDT + c]);
                    al[mi][i] = *reinterpret_cast<uint32_t*>(&Al[r * LDT + c]);
                }
            }
#pragma unroll
            for (int ni = 0; ni < 8; ni++) {
                int nb = warp_n * 64 + ni * 8 + g;
                uint32_t bh0, bh1, bl0, bl1;
                {
                    int c0 = kk + 2 * t, c1 = kk + 2 * t + 8;
                    bh0 = *reinterpret_cast<uint32_t*>(&Bh[nb * LDT + c0]);
                    bh1 = *reinterpret_cast<uint32_t*>(&Bh[nb * LDT + c1]);
                    bl0 = *reinterpret_cast<uint32_t*>(&Bl[nb * LDT + c0]);
                    bl1 = *reinterpret_cast<uint32_t*>(&Bl[nb * LDT + c1]);
                }
#pragma unroll
                for (int mi = 0; mi < 2; mi++) {
                    mma_bf16(acc[mi][ni], ah[mi], bh0, bh1);
                    mma_bf16(acc[mi][ni], ah[mi], bl0, bl1);
                    mma_bf16(acc[mi][ni], al[mi], bh0, bh1);
                }
            }
        }
        __syncthreads();
    }

#pragma unroll
    for (int mi = 0; mi < 2; mi++) {
#pragma unroll
        for (int ni = 0; ni < 8; ni++) {
            int row0 = block_row + warp_m * 32 + mi * 16 + g;
            int col  = block_col + warp_n * 64 + ni * 8 + 2 * t;
            if (row0 < N_NODES) {
                *reinterpret_cast<float2*>(g_ft + (size_t)row0 * FDIM + col) =
                    make_float2(acc[mi][ni][0], acc[mi][ni][1]);
            }
            int row1 = row0 + 8;
            if (row1 < N_NODES) {
                *reinterpret_cast<float2*>(g_ft + (size_t)row1 * FDIM + col) =
                    make_float2(acc[mi][ni][2], acc[mi][ni][3]);
            }
        }
    }
}

// ---------------- 2) per-node attention terms a1/a2 --------------------------
__global__ void a1a2_kernel(const float* __restrict__ attn_l,
                            const float* __restrict__ attn_r)
{
    int gtid = blockIdx.x * blockDim.x + threadIdx.x;
    int warp = gtid >> 5;
    int lane = gtid & 31;
    if (warp >= N_NODES * HEADS) return;
    int n = warp >> 2;
    int h = warp & 3;
    const float* row = g_ft + (size_t)n * FDIM + h * OUT_DIM;
    const float* al  = attn_l + h * OUT_DIM;
    const float* ar  = attn_r + h * OUT_DIM;
    float v0 = row[lane], v1 = row[lane + 32];
    float s1 = v0 * al[lane] + v1 * al[lane + 32];
    float s2 = v0 * ar[lane] + v1 * ar[lane + 32];
#pragma unroll
    for (int o = 16; o > 0; o >>= 1) {
        s1 += __shfl_xor_sync(0xFFFFFFFFu, s1, o);
        s2 += __shfl_xor_sync(0xFFFFFFFFu, s2, o);
    }
    if (lane == 0) {
        g_a1[n * HEADS + h] = s1;
        g_a2[n * HEADS + h] = s2;
    }
}

// ---------------- 3) CSR build: histogram, scan, scatter ---------------------
__global__ void hist_kernel(const int* __restrict__ dst) {
    int e = blockIdx.x * blockDim.x + threadIdx.x;
    if (e < N_EDGES) atomicAdd(&g_deg[dst[e]], 1);
}

__global__ __launch_bounds__(SCAN_TPB)
void scan1_kernel() {
    __shared__ int s[SCAN_TPB];
    int tid = threadIdx.x;
    int i = blockIdx.x * SCAN_TPB + tid;
    int v = (i < N_NODES) ? g_deg[i] : 0;
    s[tid] = v;
    __syncthreads();
#pragma unroll
    for (int off = 1; off < SCAN_TPB; off <<= 1) {
        int t = (tid >= off) ? s[tid - off] : 0;
        __syncthreads();
        s[tid] += t;
        __syncthreads();
    }
    if (i < N_NODES) g_rowstart[i] = s[tid] - v;
    if (tid == SCAN_TPB - 1) g_bsum[blockIdx.x] = s[tid];
}

__global__ __launch_bounds__(SCAN_TPB)
void scan2_kernel() {
    __shared__ int s[SCAN_TPB];
    int tid = threadIdx.x;
    int v = (tid < SCAN_NB) ? g_bsum[tid] : 0;
    s[tid] = v;
    __syncthreads();
#pragma unroll
    for (int off = 1; off < SCAN_TPB; off <<= 1) {
        int t = (tid >= off) ? s[tid - off] : 0;
        __syncthreads();
        s[tid] += t;
        __syncthreads();
    }
    if (tid < SCAN_NB) g_bscan[tid] = s[tid] - v;
}

__global__ __launch_bounds__(SCAN_TPB)
void scan3_kernel() {
    int i = blockIdx.x * SCAN_TPB + threadIdx.x;
    if (i < N_NODES) {
        int r = g_rowstart[i] + g_bscan[blockIdx.x];
        g_rowstart[i] = r;
        g_cursor[i] = r;
    }
}

__global__ void scatter_kernel(const int* __restrict__ src,
                               const int* __restrict__ dst) {
    int e = blockIdx.x * blockDim.x + threadIdx.x;
    if (e >= N_EDGES) return;
    int slot = atomicAdd(&g_cursor[dst[e]], 1);
    g_csr_src[slot] = src[e];
}

// ---------------- 4) warp-per-node fused GAT aggregation ---------------------
__device__ __forceinline__ float lrelu(float x) {
    return (x > 0.0f) ? x : ALPHA * x;
}
__device__ __forceinline__ float wred_max(float v) {
#pragma unroll
    for (int o = 16; o > 0; o >>= 1)
        v = fmaxf(v, __shfl_xor_sync(0xFFFFFFFFu, v, o));
    return v;
}
__device__ __forceinline__ float wred_sum(float v) {
#pragma unroll
    for (int o = 16; o > 0; o >>= 1)
        v += __shfl_xor_sync(0xFFFFFFFFu, v, o);
    return v;
}

#define GAT_WPB 8   // warps per block

__global__ __launch_bounds__(GAT_WPB * 32)
void gat_warp_kernel(float* __restrict__ out)
{
    const int wid  = threadIdx.x >> 5;
    const int lane = threadIdx.x & 31;
    const int n    = blockIdx.x * GAT_WPB + wid;   // 50000 = 6250*8, exact

    __shared__ float4 s_coef[GAT_WPB][32];
    __shared__ int    s_srcs[GAT_WPB][32];

    const int beg = g_rowstart[n];
    const int end = g_rowstart[n + 1];
    const int deg = end - beg;

    float4 a2v = __ldg(&reinterpret_cast<const float4*>(g_a2)[n]);

    float4 acc0 = make_float4(0.f, 0.f, 0.f, 0.f);
    float4 acc1 = make_float4(0.f, 0.f, 0.f, 0.f);
    const int h0 = lane >> 4;
    const int h1 = h0 + 2;

    if (deg <= 32) {
        // ---------- fast path: lane i owns edge i ----------
        int   s  = 0;
        float x0 = -FLT_MAX, x1 = -FLT_MAX, x2 = -FLT_MAX, x3 = -FLT_MAX;
        if (lane < deg) {
            s = __ldg(&g_csr_src[beg + lane]);
            float4 a1v = __ldg(&reinterpret_cast<const float4*>(g_a1)[s]);
            x0 = lrelu(a1v.x + a2v.x);
            x1 = lrelu(a1v.y + a2v.y);
            x2 = lrelu(a1v.z + a2v.z);
            x3 = lrelu(a1v.w + a2v.w);
        }
        float m0 = wred_max(x0), m1 = wred_max(x1);
        float m2 = wred_max(x2), m3 = wred_max(x3);
        float e0 = 0.f, e1 = 0.f, e2 = 0.f, e3 = 0.f;
        if (lane < deg) {
            e0 = __expf(x0 - m0); e1 = __expf(x1 - m1);
            e2 = __expf(x2 - m2); e3 = __expf(x3 - m3);
        }
        float i0 = 1.0f / wred_sum(e0), i1 = 1.0f / wred_sum(e1);
        float i2 = 1.0f / wred_sum(e2), i3 = 1.0f / wred_sum(e3);
        if (lane < deg) {
            s_coef[wid][lane] = make_float4(e0 * i0, e1 * i1, e2 * i2, e3 * i3);
            s_srcs[wid][lane] = s;
        }
        __syncwarp();

        const float* cf = reinterpret_cast<const float*>(&s_coef[wid][0]);
        int li = 0;
        for (; li + 2 <= deg; li += 2) {
            int sa = s_srcs[wid][li], sb = s_srcs[wid][li + 1];
            const float4* ra = reinterpret_cast<const float4*>(
                                   g_ft + (size_t)sa * FDIM) + lane;
            const float4* rb = reinterpret_cast<const float4*>(
                                   g_ft + (size_t)sb * FDIM) + lane;
            float4 va0 = __ldg(ra), va1 = __ldg(ra + 32);
            float4 vb0 = __ldg(rb), vb1 = __ldg(rb + 32);
            float ca0 = cf[li * 4 + h0],     ca1 = cf[li * 4 + h1];
            float cb0 = cf[li * 4 + 4 + h0], cb1 = cf[li * 4 + 4 + h1];
            acc0.x += ca0 * va0.x + cb0 * vb0.x;
            acc0.y += ca0 * va0.y + cb0 * vb0.y;
            acc0.z += ca0 * va0.z + cb0 * vb0.z;
            acc0.w += ca0 * va0.w + cb0 * vb0.w;
            acc1.x += ca1 * va1.x + cb1 * vb1.x;
            acc1.y += ca1 * va1.y + cb1 * vb1.y;
            acc1.z += ca1 * va1.z + cb1 * vb1.z;
            acc1.w += ca1 * va1.w + cb1 * vb1.w;
        }
        if (li < deg) {
            int sa = s_srcs[wid][li];
            const float4* ra = reinterpret_cast<const float4*>(
                                   g_ft + (size_t)sa * FDIM) + lane;
            float4 va0 = __ldg(ra), va1 = __ldg(ra + 32);
            float ca0 = cf[li * 4 + h0], ca1 = cf[li * 4 + h1];
            acc0.x += ca0 * va0.x; acc0.y += ca0 * va0.y;
            acc0.z += ca0 * va0.z; acc0.w += ca0 * va0.w;
            acc1.x += ca1 * va1.x; acc1.y += ca1 * va1.y;
            acc1.z += ca1 * va1.z; acc1.w += ca1 * va1.w;
        }
    } else {
        // ---------- slow path ----------
        float m0 = -FLT_MAX, m1 = -FLT_MAX, m2 = -FLT_MAX, m3 = -FLT_MAX;
        for (int i = beg + lane; i < end; i += 32) {
            int s = g_csr_src[i];
            float4 a1v = __ldg(&reinterpret_cast<const float4*>(g_a1)[s]);
            m0 = fmaxf(m0, lrelu(a1v.x + a2v.x));
            m1 = fmaxf(m1, lrelu(a1v.y + a2v.y));
            m2 = fmaxf(m2, lrelu(a1v.z + a2v.z));
            m3 = fmaxf(m3, lrelu(a1v.w + a2v.w));
        }
        m0 = wred_max(m0); m1 = wred_max(m1);
        m2 = wred_max(m2); m3 = wred_max(m3);
        float t0 = 0.f, t1 = 0.f, t2 = 0.f, t3 = 0.f;
        for (int i = beg + lane; i < end; i += 32) {
            int s = g_csr_src[i];
            float4 a1v = __ldg(&reinterpret_cast<const float4*>(g_a1)[s]);
            t0 += __expf(lrelu(a1v.x + a2v.x) - m0);
            t1 += __expf(lrelu(a1v.y + a2v.y) - m1);
            t2 += __expf(lrelu(a1v.z + a2v.z) - m2);
            t3 += __expf(lrelu(a1v.w + a2v.w) - m3);
        }
        float i0 = 1.0f / wred_sum(t0), i1 = 1.0f / wred_sum(t1);
        float i2 = 1.0f / wred_sum(t2), i3 = 1.0f / wred_sum(t3);

        const float* cf = reinterpret_cast<const float*>(&s_coef[wid][0]);
        for (int tb = beg; tb < end; tb += 32) {
            int cnt = min(32, end - tb);
            if (lane < cnt) {
                int s = __ldg(&g_csr_src[tb + lane]);
                float4 a1v = __ldg(&reinterpret_cast<const float4*>(g_a1)[s]);
                s_coef[wid][lane] = make_float4(
                    __expf(lrelu(a1v.x + a2v.x) - m0) * i0,
                    __expf(lrelu(a1v.y + a2v.y) - m1) * i1,
                    __expf(lrelu(a1v.z + a2v.z) - m2) * i2,
                    __expf(lrelu(a1v.w + a2v.w) - m3) * i3);
                s_srcs[wid][lane] = s;
            }
            __syncwarp();
            for (int li = 0; li < cnt; li++) {
                int sa = s_srcs[wid][li];
                const float4* ra = reinterpret_cast<const float4*>(
                                       g_ft + (size_t)sa * FDIM) + lane;
                float4 va0 = __ldg(ra), va1 = __ldg(ra + 32);
                float ca0 = cf[li * 4 + h0], ca1 = cf[li * 4 + h1];
                acc0.x += ca0 * va0.x; acc0.y += ca0 * va0.y;
                acc0.z += ca0 * va0.z; acc0.w += ca0 * va0.w;
                acc1.x += ca1 * va1.x; acc1.y += ca1 * va1.y;
                acc1.z += ca1 * va1.z; acc1.w += ca1 * va1.w;
            }
            __syncwarp();
        }
    }

    // ---- fused ELU + store ----
    float4 o0 = make_float4(
        acc0.x > 0.f ? acc0.x : expm1f(acc0.x),
        acc0.y > 0.f ? acc0.y : expm1f(acc0.y),
        acc0.z > 0.f ? acc0.z : expm1f(acc0.z),
        acc0.w > 0.f ? acc0.w : expm1f(acc0.w));
    float4 o1 = make_float4(
        acc1.x > 0.f ? acc1.x : expm1f(acc1.x),
        acc1.y > 0.f ? acc1.y : expm1f(acc1.y),
        acc1.z > 0.f ? acc1.z : expm1f(acc1.z),
        acc1.w > 0.f ? acc1.w : expm1f(acc1.w));
    float4* orow = reinterpret_cast<float4*>(out + (size_t)n * FDIM) + lane;
    orow[0]  = o0;
    orow[32] = o1;
}

// ---------------- launch ------------------------------------------------------
extern "C" void kernel_launch(void* const* d_in, const int* in_sizes, int n_in,
                              void* d_out, int out_size)
{
    const float* feat   = (const float*)d_in[0];
    const int*   src    = (const int*)  d_in[1];
    const int*   dst    = (const int*)  d_in[2];
    const float* W      = (const float*)d_in[3];
    const float* attn_l = (const float*)d_in[4];
    const float* attn_r = (const float*)d_in[5];
    float* out = (float*)d_out;

    const int TPB = 256;

    // one-time side stream + fork/join events (host objects, not device memory;
    // created on the first (uncaptured) correctness call, reused thereafter)
    static cudaStream_t s_side = nullptr;
    static cudaEvent_t  ev_fork = nullptr, ev_join = nullptr;
    if (s_side == nullptr) {
        cudaStreamCreateWithFlags(&s_side, cudaStreamNonBlocking);
        cudaEventCreateWithFlags(&ev_fork, cudaEventDisableTiming);
        cudaEventCreateWithFlags(&ev_join, cudaEventDisableTiming);
    }

    // ---- fork: side stream runs GEMM -> a1a2; main stream runs CSR build ----
    cudaEventRecord(ev_fork, 0);
    cudaStreamWaitEvent(s_side, ev_fork, 0);

    // side stream: projection GEMM + attention terms
    {
        dim3 grid((N_NODES + GBM - 1) / GBM, FDIM / GBN);
        gemm_bf16x3_kernel<<<grid, 256, 0, s_side>>>(feat, W);
        int threads = N_NODES * HEADS * 32;
        a1a2_kernel<<<(threads + TPB - 1) / TPB, TPB, 0, s_side>>>(attn_l, attn_r);
    }

    // main stream: CSR build
    init_kernel<<<(N_NODES + TPB - 1) / TPB, TPB>>>();
    hist_kernel<<<(N_EDGES + TPB - 1) / TPB, TPB>>>(dst);
    scan1_kernel<<<SCAN_NB, SCAN_TPB>>>();
    scan2_kernel<<<1, SCAN_TPB>>>();
    scan3_kernel<<<SCAN_NB, SCAN_TPB>>>();
    scatter_kernel<<<(N_EDGES + TPB - 1) / TPB, TPB>>>(src, dst);

    // ---- join ----
    cudaEventRecord(ev_join, s_side);
    cudaStreamWaitEvent(0, ev_join, 0);

    // fused aggregation (needs GEMM chain + CSR chain)
    gat_warp_kernel<<<N_NODES / GAT_WPB, GAT_WPB * 32>>>(out);
}

// round 6
// speedup vs baseline: 2.8438x; 1.1203x over previous
#include <cuda_runtime.h>
#include <cuda_bf16.h>
#include <cuda_fp16.h>
#include <cstdint>
#include <cfloat>

#define N_NODES 50000
#define N_EDGES 800000
#define IN_DIM  256
#define HEADS   4
#define OUT_DIM 64
#define FDIM    256            // HEADS * OUT_DIM
#define ALPHA   0.2f

#define SCAN_TPB 256
#define SCAN_NB  ((N_NODES + SCAN_TPB - 1) / SCAN_TPB)   // 196

// ---------------- scratch (static device globals; no allocation) -------------
__device__ __half g_fth[N_NODES * FDIM];     // projected features, fp16 [N,256]
__device__ float  g_a1 [N_NODES * HEADS];    // src-side attn term [N,4]
__device__ float  g_a2 [N_NODES * HEADS];    // dst-side attn term [N,4]
__device__ int    g_deg     [N_NODES];       // in-degree histogram
__device__ int    g_rowstart[N_NODES + 1];   // CSR row offsets (by dst)
__device__ int    g_cursor  [N_NODES];       // scatter cursors
__device__ int    g_csr_src [N_EDGES];       // CSR payload: src node per slot
__device__ int    g_bsum [SCAN_NB];          // scan block sums
__device__ int    g_bscan[SCAN_NB];          // scanned block sums

// ---------------- 0) init ----------------------------------------------------
__global__ void init_kernel() {
    int i = blockIdx.x * blockDim.x + threadIdx.x;
    if (i < N_NODES) g_deg[i] = 0;
    if (i == 0) g_rowstart[N_NODES] = N_EDGES;
}

// ---------------- 1) GEMM (bf16x3 tensor cores) + fused a1a2 + fp16 store ----
#define GBM 128
#define GBN 128
#define GBK 32
#define LDT (GBK + 4)

__device__ __forceinline__ void split2(float a, float b,
                                       uint32_t& hi, uint32_t& lo) {
    __nv_bfloat16 ha = __float2bfloat16(a);
    __nv_bfloat16 hb = __float2bfloat16(b);
    __nv_bfloat162 hp; hp.x = ha; hp.y = hb;
    hi = reinterpret_cast<uint32_t&>(hp);
    __nv_bfloat162 lp;
    lp.x = __float2bfloat16(a - __bfloat162float(ha));
    lp.y = __float2bfloat16(b - __bfloat162float(hb));
    lo = reinterpret_cast<uint32_t&>(lp);
}

__device__ __forceinline__ void mma_bf16(float c[4],
                                         const uint32_t a[4],
                                         const uint32_t b0, const uint32_t b1) {
    asm volatile(
        "mma.sync.aligned.m16n8k16.row.col.f32.bf16.bf16.f32 "
        "{%0,%1,%2,%3}, {%4,%5,%6,%7}, {%8,%9}, {%0,%1,%2,%3};\n"
        : "+f"(c[0]), "+f"(c[1]), "+f"(c[2]), "+f"(c[3])
        : "r"(a[0]), "r"(a[1]), "r"(a[2]), "r"(a[3]), "r"(b0), "r"(b1));
}

__global__ __launch_bounds__(256)
void gemm_bf16x3_kernel(const float* __restrict__ A,
                        const float* __restrict__ Wm,
                        const float* __restrict__ attn_l,
                        const float* __restrict__ attn_r)
{
    __shared__ __nv_bfloat16 Ah[GBM * LDT], Al[GBM * LDT];
    __shared__ __nv_bfloat16 Bh[GBN * LDT], Bl[GBN * LDT];

    const int tid  = threadIdx.x;
    const int warp = tid >> 5, lane = tid & 31;
    const int g = lane >> 2, t = lane & 3;
    const int warp_m = warp >> 1;
    const int warp_n = warp & 1;
    const int block_row = blockIdx.x * GBM;
    const int block_col = blockIdx.y * GBN;

    float acc[2][8][4];
#pragma unroll
    for (int mi = 0; mi < 2; mi++)
#pragma unroll
        for (int ni = 0; ni < 8; ni++)
#pragma unroll
            for (int i = 0; i < 4; i++) acc[mi][ni][i] = 0.0f;

    const int lrow = tid >> 1;
    const int lk0  = (tid & 1) * 16;
    const int ar   = block_row + lrow;
    const bool aok = (ar < N_NODES);
    const int br   = block_col + lrow;

    float4 pa[4], pb[4];
#pragma unroll
    for (int q = 0; q < 4; q++) {
        int ko = lk0 + q * 4;
        pa[q] = aok ? *reinterpret_cast<const float4*>(A + (size_t)ar * IN_DIM + ko)
                    : make_float4(0.f, 0.f, 0.f, 0.f);
        pb[q] = *reinterpret_cast<const float4*>(Wm + (size_t)br * IN_DIM + ko);
    }

    for (int k0 = 0; k0 < IN_DIM; k0 += GBK) {
#pragma unroll
        for (int q = 0; q < 4; q++) {
            int ko = lk0 + q * 4;
            uint32_t h01, l01, h23, l23;
            split2(pa[q].x, pa[q].y, h01, l01);
            split2(pa[q].z, pa[q].w, h23, l23);
            *reinterpret_cast<uint32_t*>(&Ah[lrow * LDT + ko])     = h01;
            *reinterpret_cast<uint32_t*>(&Ah[lrow * LDT + ko + 2]) = h23;
            *reinterpret_cast<uint32_t*>(&Al[lrow * LDT + ko])     = l01;
            *reinterpret_cast<uint32_t*>(&Al[lrow * LDT + ko + 2]) = l23;
            split2(pb[q].x, pb[q].y, h01, l01);
            split2(pb[q].z, pb[q].w, h23, l23);
            *reinterpret_cast<uint32_t*>(&Bh[lrow * LDT + ko])     = h01;
            *reinterpret_cast<uint32_t*>(&Bh[lrow * LDT + ko + 2]) = h23;
            *reinterpret_cast<uint32_t*>(&Bl[lrow * LDT + ko])     = l01;
            *reinterpret_cast<uint32_t*>(&Bl[lrow * LDT + ko + 2]) = l23;
        }
        __syncthreads();

        int kn = k0 + GBK;
        if (kn < IN_DIM) {
#pragma unroll
            for (int q = 0; q < 4; q++) {
                int ko = kn + lk0 + q * 4;
                pa[q] = aok ? *reinterpret_cast<const float4*>(
                                  A + (size_t)ar * IN_DIM + ko)
                            : make_float4(0.f, 0.f, 0.f, 0.f);
                pb[q] = *reinterpret_cast<const float4*>(
                            Wm + (size_t)br * IN_DIM + ko);
            }
        }

#pragma unroll
        for (int kk = 0; kk < GBK; kk += 16) {
            uint32_t ah[2][4], al[2][4];
#pragma unroll
            for (int mi = 0; mi < 2; mi++) {
                int mb = warp_m * 32 + mi * 16;
#pragma unroll
                for (int i = 0; i < 4; i++) {
                    int r = mb + g + (i & 1) * 8;
                    int c = kk + 2 * t + (i >> 1) * 8;
                    ah[mi][i] = *reinterpret_cast<uint32_t*>(&Ah[r * LDT + c]);
                    al[mi][i] = *reinterpret_cast<uint32_t*>(&Al[r * LDT + c]);
                }
            }
#pragma unroll
            for (int ni = 0; ni < 8; ni++) {
                int nb = warp_n * 64 + ni * 8 + g;
                uint32_t bh0, bh1, bl0, bl1;
                {
                    int c0 = kk + 2 * t, c1 = kk + 2 * t + 8;
                    bh0 = *reinterpret_cast<uint32_t*>(&Bh[nb * LDT + c0]);
                    bh1 = *reinterpret_cast<uint32_t*>(&Bh[nb * LDT + c1]);
                    bl0 = *reinterpret_cast<uint32_t*>(&Bl[nb * LDT + c0]);
                    bl1 = *reinterpret_cast<uint32_t*>(&Bl[nb * LDT + c1]);
                }
#pragma unroll
                for (int mi = 0; mi < 2; mi++) {
                    mma_bf16(acc[mi][ni], ah[mi], bh0, bh1);
                    mma_bf16(acc[mi][ni], ah[mi], bl0, bl1);
                    mma_bf16(acc[mi][ni], al[mi], bh0, bh1);
                }
            }
        }
        __syncthreads();
    }

    // ---- epilogue 1: store fp16 features ----
#pragma unroll
    for (int mi = 0; mi < 2; mi++) {
#pragma unroll
        for (int ni = 0; ni < 8; ni++) {
            int row0 = block_row + warp_m * 32 + mi * 16 + g;
            int col  = block_col + warp_n * 64 + ni * 8 + 2 * t;
            if (row0 < N_NODES) {
                *reinterpret_cast<__half2*>(g_fth + (size_t)row0 * FDIM + col) =
                    __floats2half2_rn(acc[mi][ni][0], acc[mi][ni][1]);
            }
            int row1 = row0 + 8;
            if (row1 < N_NODES) {
                *reinterpret_cast<__half2*>(g_fth + (size_t)row1 * FDIM + col) =
                    __floats2half2_rn(acc[mi][ni][2], acc[mi][ni][3]);
            }
        }
    }

    // ---- epilogue 2: fused a1/a2 (this warp covers head h's full 64 cols) ----
    {
        const int h = blockIdx.y * 2 + warp_n;
        float p1[4] = {0.f, 0.f, 0.f, 0.f};
        float p2[4] = {0.f, 0.f, 0.f, 0.f};
#pragma unroll
        for (int ni = 0; ni < 8; ni++) {
            int d0 = ni * 8 + 2 * t;
            float al0 = attn_l[h * OUT_DIM + d0];
            float al1 = attn_l[h * OUT_DIM + d0 + 1];
            float ar0 = attn_r[h * OUT_DIM + d0];
            float ar1 = attn_r[h * OUT_DIM + d0 + 1];
#pragma unroll
            for (int mi = 0; mi < 2; mi++) {
                p1[mi * 2 + 0] += acc[mi][ni][0] * al0 + acc[mi][ni][1] * al1;
                p1[mi * 2 + 1] += acc[mi][ni][2] * al0 + acc[mi][ni][3] * al1;
                p2[mi * 2 + 0] += acc[mi][ni][0] * ar0 + acc[mi][ni][1] * ar1;
                p2[mi * 2 + 1] += acc[mi][ni][2] * ar0 + acc[mi][ni][3] * ar1;
            }
        }
        // reduce across the 4 t-lanes (lane bits 0-1)
#pragma unroll
        for (int j = 0; j < 4; j++) {
            p1[j] += __shfl_xor_sync(0xFFFFFFFFu, p1[j], 1);
            p1[j] += __shfl_xor_sync(0xFFFFFFFFu, p1[j], 2);
            p2[j] += __shfl_xor_sync(0xFFFFFFFFu, p2[j], 1);
            p2[j] += __shfl_xor_sync(0xFFFFFFFFu, p2[j], 2);
        }
        if (t == 0) {
            int r0 = block_row + warp_m * 32 + g;
#pragma unroll
            for (int j = 0; j < 4; j++) {
                int row = r0 + (j >> 1) * 16 + (j & 1) * 8;
                if (row < N_NODES) {
                    g_a1[row * HEADS + h] = p1[j];
                    g_a2[row * HEADS + h] = p2[j];
                }
            }
        }
    }
}

// ---------------- 3) CSR build: histogram, scan, scatter ---------------------
__global__ void hist_kernel(const int* __restrict__ dst) {
    int e = blockIdx.x * blockDim.x + threadIdx.x;
    if (e < N_EDGES) atomicAdd(&g_deg[dst[e]], 1);
}

__global__ __launch_bounds__(SCAN_TPB)
void scan1_kernel() {
    __shared__ int s[SCAN_TPB];
    int tid = threadIdx.x;
    int i = blockIdx.x * SCAN_TPB + tid;
    int v = (i < N_NODES) ? g_deg[i] : 0;
    s[tid] = v;
    __syncthreads();
#pragma unroll
    for (int off = 1; off < SCAN_TPB; off <<= 1) {
        int t = (tid >= off) ? s[tid - off] : 0;
        __syncthreads();
        s[tid] += t;
        __syncthreads();
    }
    if (i < N_NODES) g_rowstart[i] = s[tid] - v;
    if (tid == SCAN_TPB - 1) g_bsum[blockIdx.x] = s[tid];
}

__global__ __launch_bounds__(SCAN_TPB)
void scan2_kernel() {
    __shared__ int s[SCAN_TPB];
    int tid = threadIdx.x;
    int v = (tid < SCAN_NB) ? g_bsum[tid] : 0;
    s[tid] = v;
    __syncthreads();
#pragma unroll
    for (int off = 1; off < SCAN_TPB; off <<= 1) {
        int t = (tid >= off) ? s[tid - off] : 0;
        __syncthreads();
        s[tid] += t;
        __syncthreads();
    }
    if (tid < SCAN_NB) g_bscan[tid] = s[tid] - v;
}

__global__ __launch_bounds__(SCAN_TPB)
void scan3_kernel() {
    int i = blockIdx.x * SCAN_TPB + threadIdx.x;
    if (i < N_NODES) {
        int r = g_rowstart[i] + g_bscan[blockIdx.x];
        g_rowstart[i] = r;
        g_cursor[i] = r;
    }
}

__global__ void scatter_kernel(const int* __restrict__ src,
                               const int* __restrict__ dst) {
    int e = blockIdx.x * blockDim.x + threadIdx.x;
    if (e >= N_EDGES) return;
    int slot = atomicAdd(&g_cursor[dst[e]], 1);
    g_csr_src[slot] = src[e];
}

// ---------------- 4) warp-per-node fused GAT aggregation (fp16 gather) -------
__device__ __forceinline__ float lrelu(float x) {
    return (x > 0.0f) ? x : ALPHA * x;
}
__device__ __forceinline__ float wred_max(float v) {
#pragma unroll
    for (int o = 16; o > 0; o >>= 1)
        v = fmaxf(v, __shfl_xor_sync(0xFFFFFFFFu, v, o));
    return v;
}
__device__ __forceinline__ float wred_sum(float v) {
#pragma unroll
    for (int o = 16; o > 0; o >>= 1)
        v += __shfl_xor_sync(0xFFFFFFFFu, v, o);
    return v;
}
__device__ __forceinline__ void acc_row(float acc[8], float c, uint4 v) {
    const __half2* hp = reinterpret_cast<const __half2*>(&v);
#pragma unroll
    for (int k = 0; k < 4; k++) {
        float2 f = __half22float2(hp[k]);
        acc[2 * k]     += c * f.x;
        acc[2 * k + 1] += c * f.y;
    }
}

#define GAT_WPB 8   // warps per block

__global__ __launch_bounds__(GAT_WPB * 32)
void gat_warp_kernel(float* __restrict__ out)
{
    const int wid  = threadIdx.x >> 5;
    const int lane = threadIdx.x & 31;
    const int n    = blockIdx.x * GAT_WPB + wid;   // 50000 = 6250*8, exact

    __shared__ float4 s_coef[GAT_WPB][32];
    __shared__ int    s_srcs[GAT_WPB][32];

    const int beg = g_rowstart[n];
    const int end = g_rowstart[n + 1];
    const int deg = end - beg;

    float4 a2v = __ldg(&reinterpret_cast<const float4*>(g_a2)[n]);

    float acc[8];
#pragma unroll
    for (int k = 0; k < 8; k++) acc[k] = 0.0f;
    const int hh = lane >> 3;          // lane owns cols [8*lane, 8*lane+8) -> one head

    if (deg <= 32) {
        // ---------- fast path: lane i owns edge i ----------
        int   s  = 0;
        float x0 = -FLT_MAX, x1 = -FLT_MAX, x2 = -FLT_MAX, x3 = -FLT_MAX;
        if (lane < deg) {
            s = __ldg(&g_csr_src[beg + lane]);
            float4 a1v = __ldg(&reinterpret_cast<const float4*>(g_a1)[s]);
            x0 = lrelu(a1v.x + a2v.x);
            x1 = lrelu(a1v.y + a2v.y);
            x2 = lrelu(a1v.z + a2v.z);
            x3 = lrelu(a1v.w + a2v.w);
        }
        float m0 = wred_max(x0), m1 = wred_max(x1);
        float m2 = wred_max(x2), m3 = wred_max(x3);
        float e0 = 0.f, e1 = 0.f, e2 = 0.f, e3 = 0.f;
        if (lane < deg) {
            e0 = __expf(x0 - m0); e1 = __expf(x1 - m1);
            e2 = __expf(x2 - m2); e3 = __expf(x3 - m3);
        }
        float i0 = 1.0f / wred_sum(e0), i1 = 1.0f / wred_sum(e1);
        float i2 = 1.0f / wred_sum(e2), i3 = 1.0f / wred_sum(e3);
        if (lane < deg) {
            s_coef[wid][lane] = make_float4(e0 * i0, e1 * i1, e2 * i2, e3 * i3);
            s_srcs[wid][lane] = s;
        }
        __syncwarp();

        const float* cf = reinterpret_cast<const float*>(&s_coef[wid][0]);
        int li = 0;
        for (; li + 2 <= deg; li += 2) {
            int sa = s_srcs[wid][li], sb = s_srcs[wid][li + 1];
            const uint4* ra = reinterpret_cast<const uint4*>(
                                  g_fth + (size_t)sa * FDIM) + lane;
            const uint4* rb = reinterpret_cast<const uint4*>(
                                  g_fth + (size_t)sb * FDIM) + lane;
            uint4 va = __ldg(ra);
            uint4 vb = __ldg(rb);
            acc_row(acc, cf[li * 4 + hh], va);
            acc_row(acc, cf[li * 4 + 4 + hh], vb);
        }
        if (li < deg) {
            int sa = s_srcs[wid][li];
            uint4 va = __ldg(reinterpret_cast<const uint4*>(
                                 g_fth + (size_t)sa * FDIM) + lane);
            acc_row(acc, cf[li * 4 + hh], va);
        }
    } else {
        // ---------- slow path: generic strided 2-pass + 32-edge tiles ----------
        float m0 = -FLT_MAX, m1 = -FLT_MAX, m2 = -FLT_MAX, m3 = -FLT_MAX;
        for (int i = beg + lane; i < end; i += 32) {
            int s = g_csr_src[i];
            float4 a1v = __ldg(&reinterpret_cast<const float4*>(g_a1)[s]);
            m0 = fmaxf(m0, lrelu(a1v.x + a2v.x));
            m1 = fmaxf(m1, lrelu(a1v.y + a2v.y));
            m2 = fmaxf(m2, lrelu(a1v.z + a2v.z));
            m3 = fmaxf(m3, lrelu(a1v.w + a2v.w));
        }
        m0 = wred_max(m0); m1 = wred_max(m1);
        m2 = wred_max(m2); m3 = wred_max(m3);
        float t0 = 0.f, t1 = 0.f, t2 = 0.f, t3 = 0.f;
        for (int i = beg + lane; i < end; i += 32) {
            int s = g_csr_src[i];
            float4 a1v = __ldg(&reinterpret_cast<const float4*>(g_a1)[s]);
            t0 += __expf(lrelu(a1v.x + a2v.x) - m0);
            t1 += __expf(lrelu(a1v.y + a2v.y) - m1);
            t2 += __expf(lrelu(a1v.z + a2v.z) - m2);
            t3 += __expf(lrelu(a1v.w + a2v.w) - m3);
        }
        float i0 = 1.0f / wred_sum(t0), i1 = 1.0f / wred_sum(t1);
        float i2 = 1.0f / wred_sum(t2), i3 = 1.0f / wred_sum(t3);

        const float* cf = reinterpret_cast<const float*>(&s_coef[wid][0]);
        for (int tb = beg; tb < end; tb += 32) {
            int cnt = min(32, end - tb);
            if (lane < cnt) {
                int s = __ldg(&g_csr_src[tb + lane]);
                float4 a1v = __ldg(&reinterpret_cast<const float4*>(g_a1)[s]);
                s_coef[wid][lane] = make_float4(
                    __expf(lrelu(a1v.x + a2v.x) - m0) * i0,
                    __expf(lrelu(a1v.y + a2v.y) - m1) * i1,
                    __expf(lrelu(a1v.z + a2v.z) - m2) * i2,
                    __expf(lrelu(a1v.w + a2v.w) - m3) * i3);
                s_srcs[wid][lane] = s;
            }
            __syncwarp();
            for (int li = 0; li < cnt; li++) {
                int sa = s_srcs[wid][li];
                uint4 va = __ldg(reinterpret_cast<const uint4*>(
                                     g_fth + (size_t)sa * FDIM) + lane);
                acc_row(acc, cf[li * 4 + hh], va);
            }
            __syncwarp();
        }
    }

    // ---- fused ELU + store (lane owns cols 8*lane..8*lane+7) ----
    float4 o0 = make_float4(
        acc[0] > 0.f ? acc[0] : expm1f(acc[0]),
        acc[1] > 0.f ? acc[1] : expm1f(acc[1]),
        acc[2] > 0.f ? acc[2] : expm1f(acc[2]),
        acc[3] > 0.f ? acc[3] : expm1f(acc[3]));
    float4 o1 = make_float4(
        acc[4] > 0.f ? acc[4] : expm1f(acc[4]),
        acc[5] > 0.f ? acc[5] : expm1f(acc[5]),
        acc[6] > 0.f ? acc[6] : expm1f(acc[6]),
        acc[7] > 0.f ? acc[7] : expm1f(acc[7]));
    float4* op = reinterpret_cast<float4*>(out + (size_t)n * FDIM + 8 * lane);
    op[0] = o0;
    op[1] = o1;
}

// ---------------- launch ------------------------------------------------------
extern "C" void kernel_launch(void* const* d_in, const int* in_sizes, int n_in,
                              void* d_out, int out_size)
{
    const float* feat   = (const float*)d_in[0];
    const int*   src    = (const int*)  d_in[1];
    const int*   dst    = (const int*)  d_in[2];
    const float* W      = (const float*)d_in[3];
    const float* attn_l = (const float*)d_in[4];
    const float* attn_r = (const float*)d_in[5];
    float* out = (float*)d_out;

    const int TPB = 256;

    static cudaStream_t s_side = nullptr;
    static cudaEvent_t  ev_fork = nullptr, ev_join = nullptr;
    if (s_side == nullptr) {
        cudaStreamCreateWithFlags(&s_side, cudaStreamNonBlocking);
        cudaEventCreateWithFlags(&ev_fork, cudaEventDisableTiming);
        cudaEventCreateWithFlags(&ev_join, cudaEventDisableTiming);
    }

    // ---- fork: side stream runs GEMM(+a1a2); main stream runs CSR build ----
    cudaEventRecord(ev_fork, 0);
    cudaStreamWaitEvent(s_side, ev_fork, 0);

    {
        dim3 grid((N_NODES + GBM - 1) / GBM, FDIM / GBN);
        gemm_bf16x3_kernel<<<grid, 256, 0, s_side>>>(feat, W, attn_l, attn_r);
    }

    init_kernel<<<(N_NODES + TPB - 1) / TPB, TPB>>>();
    hist_kernel<<<(N_EDGES + TPB - 1) / TPB, TPB>>>(dst);
    scan1_kernel<<<SCAN_NB, SCAN_TPB>>>();
    scan2_kernel<<<1, SCAN_TPB>>>();
    scan3_kernel<<<SCAN_NB, SCAN_TPB>>>();
    scatter_kernel<<<(N_EDGES + TPB - 1) / TPB, TPB>>>(src, dst);

    // ---- join ----
    cudaEventRecord(ev_join, s_side);
    cudaStreamWaitEvent(0, ev_join, 0);

    gat_warp_kernel<<<N_NODES / GAT_WPB, GAT_WPB * 32>>>(out);
}

// round 7
// speedup vs baseline: 3.1757x; 1.1167x over previous
#include <cuda_runtime.h>
#include <cuda_fp16.h>
#include <cstdint>
#include <cfloat>

#define N_NODES 50000
#define N_EDGES 800000
#define IN_DIM  256
#define HEADS   4
#define OUT_DIM 64
#define FDIM    256            // HEADS * OUT_DIM
#define ALPHA   0.2f

#define SCAN_TPB 256
#define SCAN_NB  ((N_NODES + SCAN_TPB - 1) / SCAN_TPB)   // 196

// ---------------- scratch (static device globals; no allocation) -------------
__device__ __half g_fth[N_NODES * FDIM];     // projected features, fp16 [N,256]
__device__ float  g_a1 [N_NODES * HEADS];    // src-side attn term [N,4]
__device__ float  g_a2 [N_NODES * HEADS];    // dst-side attn term [N,4]
__device__ int    g_deg     [N_NODES];       // in-degree histogram
__device__ int    g_rowstart[N_NODES + 1];   // CSR row offsets (by dst)
__device__ int    g_cursor  [N_NODES];       // scatter cursors
__device__ int    g_csr_src [N_EDGES];       // CSR payload: src node per slot
__device__ int    g_bsum [SCAN_NB];          // scan block sums
__device__ int    g_bscan[SCAN_NB];          // scanned block sums

// ---------------- 0) init ----------------------------------------------------
__global__ void init_kernel() {
    int i = blockIdx.x * blockDim.x + threadIdx.x;
    if (i < N_NODES) g_deg[i] = 0;
    if (i == 0) g_rowstart[N_NODES] = N_EDGES;
}

// ---------------- 1) GEMM (fp16 split-A tensor cores) + fused a1a2 -----------
// A split into Ah+Al (fp16 pair, ~22 mantissa bits); B kept as single fp16 Bh.
// D = Ah*Bh + Al*Bh = A*Bh  -> only error is fp16 truncation of B (~2^-12).
#define GBM 128
#define GBN 128
#define GBK 32
#define LDT (GBK + 4)

__device__ __forceinline__ void split2h(float a, float b,
                                        uint32_t& hi, uint32_t& lo) {
    __half2 hp = __floats2half2_rn(a, b);
    hi = reinterpret_cast<uint32_t&>(hp);
    __half2 lp = __floats2half2_rn(a - __half2float(__low2half(hp)),
                                   b - __half2float(__high2half(hp)));
    lo = reinterpret_cast<uint32_t&>(lp);
}

__device__ __forceinline__ void mma_f16(float c[4],
                                        const uint32_t a[4],
                                        const uint32_t b0, const uint32_t b1) {
    asm volatile(
        "mma.sync.aligned.m16n8k16.row.col.f32.f16.f16.f32 "
        "{%0,%1,%2,%3}, {%4,%5,%6,%7}, {%8,%9}, {%0,%1,%2,%3};\n"
        : "+f"(c[0]), "+f"(c[1]), "+f"(c[2]), "+f"(c[3])
        : "r"(a[0]), "r"(a[1]), "r"(a[2]), "r"(a[3]), "r"(b0), "r"(b1));
}

__global__ __launch_bounds__(256)
void gemm_f16x2_kernel(const float* __restrict__ A,
                       const float* __restrict__ Wm,
                       const float* __restrict__ attn_l,
                       const float* __restrict__ attn_r)
{
    __shared__ __half Ah[GBM * LDT], Al[GBM * LDT];
    __shared__ __half Bh[GBN * LDT];

    const int tid  = threadIdx.x;
    const int warp = tid >> 5, lane = tid & 31;
    const int g = lane >> 2, t = lane & 3;
    const int warp_m = warp >> 1;
    const int warp_n = warp & 1;
    const int block_row = blockIdx.x * GBM;
    const int block_col = blockIdx.y * GBN;

    float acc[2][8][4];
#pragma unroll
    for (int mi = 0; mi < 2; mi++)
#pragma unroll
        for (int ni = 0; ni < 8; ni++)
#pragma unroll
            for (int i = 0; i < 4; i++) acc[mi][ni][i] = 0.0f;

    const int lrow = tid >> 1;
    const int lk0  = (tid & 1) * 16;
    const int ar   = block_row + lrow;
    const bool aok = (ar < N_NODES);
    const int br   = block_col + lrow;

    float4 pa[4], pb[4];
#pragma unroll
    for (int q = 0; q < 4; q++) {
        int ko = lk0 + q * 4;
        pa[q] = aok ? *reinterpret_cast<const float4*>(A + (size_t)ar * IN_DIM + ko)
                    : make_float4(0.f, 0.f, 0.f, 0.f);
        pb[q] = *reinterpret_cast<const float4*>(Wm + (size_t)br * IN_DIM + ko);
    }

    for (int k0 = 0; k0 < IN_DIM; k0 += GBK) {
        // ---- split current prefetched tile into smem ----
#pragma unroll
        for (int q = 0; q < 4; q++) {
            int ko = lk0 + q * 4;
            uint32_t h01, l01, h23, l23;
            split2h(pa[q].x, pa[q].y, h01, l01);
            split2h(pa[q].z, pa[q].w, h23, l23);
            *reinterpret_cast<uint32_t*>(&Ah[lrow * LDT + ko])     = h01;
            *reinterpret_cast<uint32_t*>(&Ah[lrow * LDT + ko + 2]) = h23;
            *reinterpret_cast<uint32_t*>(&Al[lrow * LDT + ko])     = l01;
            *reinterpret_cast<uint32_t*>(&Al[lrow * LDT + ko + 2]) = l23;
            __half2 b01 = __floats2half2_rn(pb[q].x, pb[q].y);
            __half2 b23 = __floats2half2_rn(pb[q].z, pb[q].w);
            *reinterpret_cast<uint32_t*>(&Bh[lrow * LDT + ko])     =
                reinterpret_cast<uint32_t&>(b01);
            *reinterpret_cast<uint32_t*>(&Bh[lrow * LDT + ko + 2]) =
                reinterpret_cast<uint32_t&>(b23);
        }
        __syncthreads();

        // ---- prefetch next tile ----
        int kn = k0 + GBK;
        if (kn < IN_DIM) {
#pragma unroll
            for (int q = 0; q < 4; q++) {
                int ko = kn + lk0 + q * 4;
                pa[q] = aok ? *reinterpret_cast<const float4*>(
                                  A + (size_t)ar * IN_DIM + ko)
                            : make_float4(0.f, 0.f, 0.f, 0.f);
                pb[q] = *reinterpret_cast<const float4*>(
                            Wm + (size_t)br * IN_DIM + ko);
            }
        }

        // ---- MMA compute on current smem tile ----
#pragma unroll
        for (int kk = 0; kk < GBK; kk += 16) {
            uint32_t ah[2][4], al[2][4];
#pragma unroll
            for (int mi = 0; mi < 2; mi++) {
                int mb = warp_m * 32 + mi * 16;
#pragma unroll
                for (int i = 0; i < 4; i++) {
                    int r = mb + g + (i & 1) * 8;
                    int c = kk + 2 * t + (i >> 1) * 8;
                    ah[mi][i] = *reinterpret_cast<uint32_t*>(&Ah[r * LDT + c]);
                    al[mi][i] = *reinterpret_cast<uint32_t*>(&Al[r * LDT + c]);
                }
            }
#pragma unroll
            for (int ni = 0; ni < 8; ni++) {
                int nb = warp_n * 64 + ni * 8 + g;
                int c0 = kk + 2 * t, c1 = kk + 2 * t + 8;
                uint32_t bh0 = *reinterpret_cast<uint32_t*>(&Bh[nb * LDT + c0]);
                uint32_t bh1 = *reinterpret_cast<uint32_t*>(&Bh[nb * LDT + c1]);
#pragma unroll
                for (int mi = 0; mi < 2; mi++) {
                    mma_f16(acc[mi][ni], ah[mi], bh0, bh1);
                    mma_f16(acc[mi][ni], al[mi], bh0, bh1);
                }
            }
        }
        __syncthreads();
    }

    // ---- epilogue 1: store fp16 features ----
#pragma unroll
    for (int mi = 0; mi < 2; mi++) {
#pragma unroll
        for (int ni = 0; ni < 8; ni++) {
            int row0 = block_row + warp_m * 32 + mi * 16 + g;
            int col  = block_col + warp_n * 64 + ni * 8 + 2 * t;
            if (row0 < N_NODES) {
                *reinterpret_cast<__half2*>(g_fth + (size_t)row0 * FDIM + col) =
                    __floats2half2_rn(acc[mi][ni][0], acc[mi][ni][1]);
            }
            int row1 = row0 + 8;
            if (row1 < N_NODES) {
                *reinterpret_cast<__half2*>(g_fth + (size_t)row1 * FDIM + col) =
                    __floats2half2_rn(acc[mi][ni][2], acc[mi][ni][3]);
            }
        }
    }

    // ---- epilogue 2: fused a1/a2 (this warp covers head h's full 64 cols) ----
    {
        const int h = blockIdx.y * 2 + warp_n;
        float p1[4] = {0.f, 0.f, 0.f, 0.f};
        float p2[4] = {0.f, 0.f, 0.f, 0.f};
#pragma unroll
        for (int ni = 0; ni < 8; ni++) {
            int d0 = ni * 8 + 2 * t;
            float al0 = attn_l[h * OUT_DIM + d0];
            float al1 = attn_l[h * OUT_DIM + d0 + 1];
            float ar0 = attn_r[h * OUT_DIM + d0];
            float ar1 = attn_r[h * OUT_DIM + d0 + 1];
#pragma unroll
            for (int mi = 0; mi < 2; mi++) {
                p1[mi * 2 + 0] += acc[mi][ni][0] * al0 + acc[mi][ni][1] * al1;
                p1[mi * 2 + 1] += acc[mi][ni][2] * al0 + acc[mi][ni][3] * al1;
                p2[mi * 2 + 0] += acc[mi][ni][0] * ar0 + acc[mi][ni][1] * ar1;
                p2[mi * 2 + 1] += acc[mi][ni][2] * ar0 + acc[mi][ni][3] * ar1;
            }
        }
#pragma unroll
        for (int j = 0; j < 4; j++) {
            p1[j] += __shfl_xor_sync(0xFFFFFFFFu, p1[j], 1);
            p1[j] += __shfl_xor_sync(0xFFFFFFFFu, p1[j], 2);
            p2[j] += __shfl_xor_sync(0xFFFFFFFFu, p2[j], 1);
            p2[j] += __shfl_xor_sync(0xFFFFFFFFu, p2[j], 2);
        }
        if (t == 0) {
            int r0 = block_row + warp_m * 32 + g;
#pragma unroll
            for (int j = 0; j < 4; j++) {
                int row = r0 + (j >> 1) * 16 + (j & 1) * 8;
                if (row < N_NODES) {
                    g_a1[row * HEADS + h] = p1[j];
                    g_a2[row * HEADS + h] = p2[j];
                }
            }
        }
    }
}

// ---------------- 3) CSR build: histogram, scan, scatter ---------------------
__global__ void hist_kernel(const int* __restrict__ dst) {
    int e = blockIdx.x * blockDim.x + threadIdx.x;
    if (e < N_EDGES) atomicAdd(&g_deg[dst[e]], 1);
}

__global__ __launch_bounds__(SCAN_TPB)
void scan1_kernel() {
    __shared__ int s[SCAN_TPB];
    int tid = threadIdx.x;
    int i = blockIdx.x * SCAN_TPB + tid;
    int v = (i < N_NODES) ? g_deg[i] : 0;
    s[tid] = v;
    __syncthreads();
#pragma unroll
    for (int off = 1; off < SCAN_TPB; off <<= 1) {
        int t = (tid >= off) ? s[tid - off] : 0;
        __syncthreads();
        s[tid] += t;
        __syncthreads();
    }
    if (i < N_NODES) g_rowstart[i] = s[tid] - v;
    if (tid == SCAN_TPB - 1) g_bsum[blockIdx.x] = s[tid];
}

__global__ __launch_bounds__(SCAN_TPB)
void scan2_kernel() {
    __shared__ int s[SCAN_TPB];
    int tid = threadIdx.x;
    int v = (tid < SCAN_NB) ? g_bsum[tid] : 0;
    s[tid] = v;
    __syncthreads();
#pragma unroll
    for (int off = 1; off < SCAN_TPB; off <<= 1) {
        int t = (tid >= off) ? s[tid - off] : 0;
        __syncthreads();
        s[tid] += t;
        __syncthreads();
    }
    if (tid < SCAN_NB) g_bscan[tid] = s[tid] - v;
}

__global__ __launch_bounds__(SCAN_TPB)
void scan3_kernel() {
    int i = blockIdx.x * SCAN_TPB + threadIdx.x;
    if (i < N_NODES) {
        int r = g_rowstart[i] + g_bscan[blockIdx.x];
        g_rowstart[i] = r;
        g_cursor[i] = r;
    }
}

__global__ void scatter_kernel(const int* __restrict__ src,
                               const int* __restrict__ dst) {
    int e = blockIdx.x * blockDim.x + threadIdx.x;
    if (e >= N_EDGES) return;
    int slot = atomicAdd(&g_cursor[dst[e]], 1);
    g_csr_src[slot] = src[e];
}

// ---------------- 4) warp-per-node fused GAT aggregation (fp16 gather) -------
__device__ __forceinline__ float lrelu(float x) {
    return (x > 0.0f) ? x : ALPHA * x;
}
__device__ __forceinline__ float wred_max(float v) {
#pragma unroll
    for (int o = 16; o > 0; o >>= 1)
        v = fmaxf(v, __shfl_xor_sync(0xFFFFFFFFu, v, o));
    return v;
}
__device__ __forceinline__ float wred_sum(float v) {
#pragma unroll
    for (int o = 16; o > 0; o >>= 1)
        v += __shfl_xor_sync(0xFFFFFFFFu, v, o);
    return v;
}
__device__ __forceinline__ void acc_row(float acc[8], float c, uint4 v) {
    const __half2* hp = reinterpret_cast<const __half2*>(&v);
#pragma unroll
    for (int k = 0; k < 4; k++) {
        float2 f = __half22float2(hp[k]);
        acc[2 * k]     += c * f.x;
        acc[2 * k + 1] += c * f.y;
    }
}

#define GAT_WPB 8   // warps per block

__global__ __launch_bounds__(GAT_WPB * 32)
void gat_warp_kernel(float* __restrict__ out)
{
    const int wid  = threadIdx.x >> 5;
    const int lane = threadIdx.x & 31;
    const int n    = blockIdx.x * GAT_WPB + wid;   // 50000 = 6250*8, exact

    __shared__ float4 s_coef[GAT_WPB][32];
    __shared__ int    s_srcs[GAT_WPB][32];

    const int beg = g_rowstart[n];
    const int end = g_rowstart[n + 1];
    const int deg = end - beg;

    float4 a2v = __ldg(&reinterpret_cast<const float4*>(g_a2)[n]);

    float acc[8];
#pragma unroll
    for (int k = 0; k < 8; k++) acc[k] = 0.0f;
    const int hh = lane >> 3;          // lane owns cols [8*lane, 8*lane+8)

    if (deg <= 32) {
        // ---------- fast path: lane i owns edge i ----------
        int   s  = 0;
        float x0 = -FLT_MAX, x1 = -FLT_MAX, x2 = -FLT_MAX, x3 = -FLT_MAX;
        if (lane < deg) {
            s = __ldg(&g_csr_src[beg + lane]);
            float4 a1v = __ldg(&reinterpret_cast<const float4*>(g_a1)[s]);
            x0 = lrelu(a1v.x + a2v.x);
            x1 = lrelu(a1v.y + a2v.y);
            x2 = lrelu(a1v.z + a2v.z);
            x3 = lrelu(a1v.w + a2v.w);
        }
        float m0 = wred_max(x0), m1 = wred_max(x1);
        float m2 = wred_max(x2), m3 = wred_max(x3);
        float e0 = 0.f, e1 = 0.f, e2 = 0.f, e3 = 0.f;
        if (lane < deg) {
            e0 = __expf(x0 - m0); e1 = __expf(x1 - m1);
            e2 = __expf(x2 - m2); e3 = __expf(x3 - m3);
        }
        float i0 = 1.0f / wred_sum(e0), i1 = 1.0f / wred_sum(e1);
        float i2 = 1.0f / wred_sum(e2), i3 = 1.0f / wred_sum(e3);
        if (lane < deg) {
            s_coef[wid][lane] = make_float4(e0 * i0, e1 * i1, e2 * i2, e3 * i3);
            s_srcs[wid][lane] = s;
        }
        __syncwarp();

        const float* cf = reinterpret_cast<const float*>(&s_coef[wid][0]);
        int li = 0;
        for (; li + 2 <= deg; li += 2) {
            int sa = s_srcs[wid][li], sb = s_srcs[wid][li + 1];
            const uint4* ra = reinterpret_cast<const uint4*>(
                                  g_fth + (size_t)sa * FDIM) + lane;
            const uint4* rb = reinterpret_cast<const uint4*>(
                                  g_fth + (size_t)sb * FDIM) + lane;
            uint4 va = __ldg(ra);
            uint4 vb = __ldg(rb);
            acc_row(acc, cf[li * 4 + hh], va);
            acc_row(acc, cf[li * 4 + 4 + hh], vb);
        }
        if (li < deg) {
            int sa = s_srcs[wid][li];
            uint4 va = __ldg(reinterpret_cast<const uint4*>(
                                 g_fth + (size_t)sa * FDIM) + lane);
            acc_row(acc, cf[li * 4 + hh], va);
        }
    } else {
        // ---------- slow path ----------
        float m0 = -FLT_MAX, m1 = -FLT_MAX, m2 = -FLT_MAX, m3 = -FLT_MAX;
        for (int i = beg + lane; i < end; i += 32) {
            int s = g_csr_src[i];
            float4 a1v = __ldg(&reinterpret_cast<const float4*>(g_a1)[s]);
            m0 = fmaxf(m0, lrelu(a1v.x + a2v.x));
            m1 = fmaxf(m1, lrelu(a1v.y + a2v.y));
            m2 = fmaxf(m2, lrelu(a1v.z + a2v.z));
            m3 = fmaxf(m3, lrelu(a1v.w + a2v.w));
        }
        m0 = wred_max(m0); m1 = wred_max(m1);
        m2 = wred_max(m2); m3 = wred_max(m3);
        float t0 = 0.f, t1 = 0.f, t2 = 0.f, t3 = 0.f;
        for (int i = beg + lane; i < end; i += 32) {
            int s = g_csr_src[i];
            float4 a1v = __ldg(&reinterpret_cast<const float4*>(g_a1)[s]);
            t0 += __expf(lrelu(a1v.x + a2v.x) - m0);
            t1 += __expf(lrelu(a1v.y + a2v.y) - m1);
            t2 += __expf(lrelu(a1v.z + a2v.z) - m2);
            t3 += __expf(lrelu(a1v.w + a2v.w) - m3);
        }
        float i0 = 1.0f / wred_sum(t0), i1 = 1.0f / wred_sum(t1);
        float i2 = 1.0f / wred_sum(t2), i3 = 1.0f / wred_sum(t3);

        const float* cf = reinterpret_cast<const float*>(&s_coef[wid][0]);
        for (int tb = beg; tb < end; tb += 32) {
            int cnt = min(32, end - tb);
            if (lane < cnt) {
                int s = __ldg(&g_csr_src[tb + lane]);
                float4 a1v = __ldg(&reinterpret_cast<const float4*>(g_a1)[s]);
                s_coef[wid][lane] = make_float4(
                    __expf(lrelu(a1v.x + a2v.x) - m0) * i0,
                    __expf(lrelu(a1v.y + a2v.y) - m1) * i1,
                    __expf(lrelu(a1v.z + a2v.z) - m2) * i2,
                    __expf(lrelu(a1v.w + a2v.w) - m3) * i3);
                s_srcs[wid][lane] = s;
            }
            __syncwarp();
            for (int li = 0; li < cnt; li++) {
                int sa = s_srcs[wid][li];
                uint4 va = __ldg(reinterpret_cast<const uint4*>(
                                     g_fth + (size_t)sa * FDIM) + lane);
                acc_row(acc, cf[li * 4 + hh], va);
            }
            __syncwarp();
        }
    }

    // ---- fused ELU + store ----
    float4 o0 = make_float4(
        acc[0] > 0.f ? acc[0] : expm1f(acc[0]),
        acc[1] > 0.f ? acc[1] : expm1f(acc[1]),
        acc[2] > 0.f ? acc[2] : expm1f(acc[2]),
        acc[3] > 0.f ? acc[3] : expm1f(acc[3]));
    float4 o1 = make_float4(
        acc[4] > 0.f ? acc[4] : expm1f(acc[4]),
        acc[5] > 0.f ? acc[5] : expm1f(acc[5]),
        acc[6] > 0.f ? acc[6] : expm1f(acc[6]),
        acc[7] > 0.f ? acc[7] : expm1f(acc[7]));
    float4* op = reinterpret_cast<float4*>(out + (size_t)n * FDIM + 8 * lane);
    op[0] = o0;
    op[1] = o1;
}

// ---------------- launch ------------------------------------------------------
extern "C" void kernel_launch(void* const* d_in, const int* in_sizes, int n_in,
                              void* d_out, int out_size)
{
    const float* feat   = (const float*)d_in[0];
    const int*   src    = (const int*)  d_in[1];
    const int*   dst    = (const int*)  d_in[2];
    const float* W      = (const float*)d_in[3];
    const float* attn_l = (const float*)d_in[4];
    const float* attn_r = (const float*)d_in[5];
    float* out = (float*)d_out;

    const int TPB = 256;

    static cudaStream_t s_side = nullptr;
    static cudaEvent_t  ev_fork = nullptr, ev_join = nullptr;
    if (s_side == nullptr) {
        cudaStreamCreateWithFlags(&s_side, cudaStreamNonBlocking);
        cudaEventCreateWithFlags(&ev_fork, cudaEventDisableTiming);
        cudaEventCreateWithFlags(&ev_join, cudaEventDisableTiming);
    }

    // ---- fork: side stream runs GEMM(+a1a2); main stream runs CSR build ----
    cudaEventRecord(ev_fork, 0);
    cudaStreamWaitEvent(s_side, ev_fork, 0);

    {
        dim3 grid((N_NODES + GBM - 1) / GBM, FDIM / GBN);
        gemm_f16x2_kernel<<<grid, 256, 0, s_side>>>(feat, W, attn_l, attn_r);
    }

    init_kernel<<<(N_NODES + TPB - 1) / TPB, TPB>>>();
    hist_kernel<<<(N_EDGES + TPB - 1) / TPB, TPB>>>(dst);
    scan1_kernel<<<SCAN_NB, SCAN_TPB>>>();
    scan2_kernel<<<1, SCAN_TPB>>>();
    scan3_kernel<<<SCAN_NB, SCAN_TPB>>>();
    scatter_kernel<<<(N_EDGES + TPB - 1) / TPB, TPB>>>(src, dst);

    // ---- join ----
    cudaEventRecord(ev_join, s_side);
    cudaStreamWaitEvent(0, ev_join, 0);

    gat_warp_kernel<<<N_NODES / GAT_WPB, GAT_WPB * 32>>>(out);
}